// round 11
// baseline (speedup 1.0000x reference)
#include <cuda_runtime.h>
#include <cuda_bf16.h>
#include <stdint.h>
#include <math.h>

// Problem shapes (fixed per reference)
#define B_ 16
#define S_ 512
#define E_ 1024
#define Q_ 8
#define L_ 4

#define BS_ROWS (B_ * S_)            // 8192
#define OUT_ELEMS (B_ * S_ * E_)     // 8388608

#define B2_KSPLIT 32                 // k-chunks for bias2

// ---------------------------------------------------------------------------
// Scratch (device globals: allocation-free rule). 16B-aligned for uint4 I/O.
// ---------------------------------------------------------------------------
__device__ __align__(16) float g_states[BS_ROWS * Q_ * 4];
__device__ __align__(16) float g_cphi[S_];
__device__ __align__(16) float g_sphi[S_];
__device__ __align__(16) float g_b2[E_];                  // bv@Wo + bo
__device__ __align__(16) float g_b2p[B2_KSPLIT * E_];     // partials

__device__ __align__(16) __nv_bfloat16 g_Xh[BS_ROWS * E_];
__device__ __align__(16) __nv_bfloat16 g_Xl[BS_ROWS * E_];
__device__ __align__(16) __nv_bfloat16 g_Wvh[E_ * E_];
__device__ __align__(16) __nv_bfloat16 g_Wvl[E_ * E_];
__device__ __align__(16) __nv_bfloat16 g_Woh[E_ * E_];
__device__ __align__(16) __nv_bfloat16 g_Wol[E_ * E_];
__device__ __align__(16) __nv_bfloat16 g_W2h[E_ * E_];    // (Wv@Wo) split
__device__ __align__(16) __nv_bfloat16 g_W2l[E_ * E_];
__device__ __align__(16) __nv_bfloat16 g_Ath[B_ * S_ * S_];
__device__ __align__(16) __nv_bfloat16 g_Atl[B_ * S_ * S_];
__device__ __align__(16) __nv_bfloat16 g_Uh[BS_ROWS * E_];  // (attn@X) split
__device__ __align__(16) __nv_bfloat16 g_Ul[BS_ROWS * E_];

__device__ __forceinline__ void split2(float v, __nv_bfloat16 &h, __nv_bfloat16 &l)
{
    h = __float2bfloat16(v);
    l = __float2bfloat16(v - __bfloat162float(h));
}

// ---------------------------------------------------------------------------
// Split fp32 -> bf16 hi/lo (vectorized) — for Wv, Wo
// ---------------------------------------------------------------------------
__global__ void split_fp32_kernel(const float* __restrict__ src,
                                  __nv_bfloat16* __restrict__ h,
                                  __nv_bfloat16* __restrict__ l, int n)
{
    int i = (blockIdx.x * blockDim.x + threadIdx.x) * 4;
    if (i >= n) return;
    float4 v = *(const float4*)(src + i);
    __nv_bfloat16 h0, h1, h2, h3, l0, l1, l2, l3;
    split2(v.x, h0, l0);
    split2(v.y, h1, l1);
    split2(v.z, h2, l2);
    split2(v.w, h3, l3);
    __nv_bfloat162 p;
    p.x = h0; p.y = h1; *(__nv_bfloat162*)(h + i)     = p;
    p.x = h2; p.y = h3; *(__nv_bfloat162*)(h + i + 2) = p;
    p.x = l0; p.y = l1; *(__nv_bfloat162*)(l + i)     = p;
    p.x = l2; p.y = l3; *(__nv_bfloat162*)(l + i + 2) = p;
}

// ---------------------------------------------------------------------------
// Precompute cos(phi)/sin(phi); b2 = bv@Wo + bo in two phases (no atomics,
// deterministic across graph replays)
// ---------------------------------------------------------------------------
__global__ void phis_kernel(const float* __restrict__ phi)
{
    int j = threadIdx.x;
    float p = phi[j];
    g_cphi[j] = cosf(p);
    g_sphi[j] = sinf(p);
}

__global__ void bias2_part_kernel(const float* __restrict__ bv,
                                  const float* __restrict__ Wo)
{
    int n  = blockIdx.x * 256 + threadIdx.x;
    int k0 = blockIdx.y * (E_ / B2_KSPLIT);
    float acc = 0.f;
    #pragma unroll 4
    for (int k = k0; k < k0 + E_ / B2_KSPLIT; k++)
        acc += bv[k] * Wo[(size_t)k * E_ + n];
    g_b2p[blockIdx.y * E_ + n] = acc;
}

__global__ void bias2_reduce_kernel(const float* __restrict__ bo)
{
    int n = blockIdx.x * 256 + threadIdx.x;
    float acc = bo[n];
    #pragma unroll
    for (int ky = 0; ky < B2_KSPLIT; ky++)
        acc += g_b2p[ky * E_ + n];
    g_b2[n] = acc;
}

// ---------------------------------------------------------------------------
// Kernel 1: fused X split + quantum_input + qubit recursion (vectorized)
// ---------------------------------------------------------------------------
__global__ __launch_bounds__(256)
void qsplit_kernel(const float* __restrict__ X,
                   const float* __restrict__ Wq,
                   const float* __restrict__ bq,
                   const float* __restrict__ theta,
                   __nv_bfloat16* __restrict__ Xh,
                   __nv_bfloat16* __restrict__ Xl)
{
    __shared__ float sWq[Q_][E_];

    const int tid  = threadIdx.x;
    const int warp = tid >> 5;
    const int lane = tid & 31;

    for (int idx = tid; idx < E_ * Q_; idx += 256) {
        int e = idx >> 3;
        int q = idx & 7;
        sWq[q][e] = Wq[idx];
    }
    __syncthreads();

    const int row = blockIdx.x * 8 + warp;
    const float* x = X + (size_t)row * E_;
    __nv_bfloat16* xh = Xh + (size_t)row * E_;
    __nv_bfloat16* xl = Xl + (size_t)row * E_;

    float acc[Q_];
    #pragma unroll
    for (int q = 0; q < Q_; q++) acc[q] = 0.f;

    for (int e0 = lane * 4; e0 < E_; e0 += 128) {
        float4 xv = *(const float4*)(x + e0);
        __nv_bfloat16 h0, h1, h2, h3, l0, l1, l2, l3;
        split2(xv.x, h0, l0);
        split2(xv.y, h1, l1);
        split2(xv.z, h2, l2);
        split2(xv.w, h3, l3);
        __nv_bfloat162 p;
        p.x = h0; p.y = h1; *(__nv_bfloat162*)(xh + e0)     = p;
        p.x = h2; p.y = h3; *(__nv_bfloat162*)(xh + e0 + 2) = p;
        p.x = l0; p.y = l1; *(__nv_bfloat162*)(xl + e0)     = p;
        p.x = l2; p.y = l3; *(__nv_bfloat162*)(xl + e0 + 2) = p;
        #pragma unroll
        for (int q = 0; q < Q_; q++) {
            float4 w = *(const float4*)&sWq[q][e0];
            acc[q] += xv.x * w.x + xv.y * w.y + xv.z * w.z + xv.w * w.w;
        }
    }
    #pragma unroll
    for (int q = 0; q < Q_; q++)
        for (int off = 16; off; off >>= 1)
            acc[q] += __shfl_xor_sync(0xffffffffu, acc[q], off);

    if (lane < Q_) {
        int q = lane;
        float ang = acc[q] + bq[q];
        float ar = cosf(0.5f * ang);
        float ai = 0.f;
        float br = sinf(0.5f * ang);
        float bi = 0.f;
        for (int l = 0; l < L_; l++) {
            float t0 = 0.5f * theta[(l * Q_ + q) * 2 + 0];
            float t1 = 0.5f * theta[(l * Q_ + q) * 2 + 1];
            float c = cosf(t0), s = sinf(t0);
            float nar = c * ar - s * br, nai = c * ai - s * bi;
            float nbr = s * ar + c * br, nbi = s * ai + c * bi;
            float cp = cosf(t1), sp = sinf(t1);
            ar = nar * cp + nai * sp;
            ai = nai * cp - nar * sp;
            br = nbr * cp - nbi * sp;
            bi = nbi * cp + nbr * sp;
        }
        float* st = g_states + (size_t)row * (Q_ * 4) + q * 4;
        st[0] = ar; st[1] = ai; st[2] = br; st[3] = bi;
    }
}

// ---------------------------------------------------------------------------
// mma.sync / cp.async helpers
// ---------------------------------------------------------------------------
__device__ __forceinline__ void ldmat_x4(unsigned int* r, const __nv_bfloat16* p)
{
    unsigned int a = (unsigned int)__cvta_generic_to_shared(p);
    asm volatile("ldmatrix.sync.aligned.m8n8.x4.shared.b16 {%0,%1,%2,%3}, [%4];"
                 : "=r"(r[0]), "=r"(r[1]), "=r"(r[2]), "=r"(r[3]) : "r"(a));
}
__device__ __forceinline__ void ldmat_x4t(unsigned int* r, const __nv_bfloat16* p)
{
    unsigned int a = (unsigned int)__cvta_generic_to_shared(p);
    asm volatile("ldmatrix.sync.aligned.m8n8.x4.trans.shared.b16 {%0,%1,%2,%3}, [%4];"
                 : "=r"(r[0]), "=r"(r[1]), "=r"(r[2]), "=r"(r[3]) : "r"(a));
}
__device__ __forceinline__ void mma16816(float* d, const unsigned int* a, const unsigned int* b)
{
    asm volatile(
        "mma.sync.aligned.m16n8k16.row.col.f32.bf16.bf16.f32 "
        "{%0,%1,%2,%3}, {%4,%5,%6,%7}, {%8,%9}, {%0,%1,%2,%3};"
        : "+f"(d[0]), "+f"(d[1]), "+f"(d[2]), "+f"(d[3])
        : "r"(a[0]), "r"(a[1]), "r"(a[2]), "r"(a[3]), "r"(b[0]), "r"(b[1]));
}
__device__ __forceinline__ void cp16p(__nv_bfloat16* dst, const __nv_bfloat16* src)
{
    unsigned int d = (unsigned int)__cvta_generic_to_shared(dst);
    asm volatile("cp.async.cg.shared.global [%0], [%1], 16;" :: "r"(d), "l"(src));
}
__device__ __forceinline__ void cp_commit()
{
    asm volatile("cp.async.commit_group;");
}
template <int N>
__device__ __forceinline__ void cp_wait()
{
    asm volatile("cp.async.wait_group %0;" :: "n"(N));
}

// ---------------------------------------------------------------------------
// bf16-split GEMM, cp.async double-buffered, TERM-MAJOR MMA ordering:
// all (mt,nt) tiles for term AhBh, then AhBl, then AlBh — consecutive MMAs
// never share an accumulator, hiding accumulator RAW latency.
// A row-major [M,K], B row-major [K,N]. 128x128x32 tile, 256 thr (8 warps).
// ---------------------------------------------------------------------------
#define A_SZ (128 * 40)
#define B_SZ (32 * 136)
#define GEMM_SMEM_BYTES ((4 * A_SZ + 4 * B_SZ) * 2)

extern __shared__ __nv_bfloat16 g_dyn[];

__global__ __launch_bounds__(256)
void gemm_bf16s(const __nv_bfloat16* __restrict__ Ah, const __nv_bfloat16* __restrict__ Al,
                const __nv_bfloat16* __restrict__ Bh, const __nv_bfloat16* __restrict__ Bl,
                const float* __restrict__ bias,
                float* __restrict__ Cf,
                __nv_bfloat16* __restrict__ Ch, __nv_bfloat16* __restrict__ Cl,
                int M, int N, int K,
                long long sA, long long sB, long long sC)
{
    __nv_bfloat16* smAh[2];
    __nv_bfloat16* smAl[2];
    __nv_bfloat16* smBh[2];
    __nv_bfloat16* smBl[2];
    smAh[0] = g_dyn;
    smAh[1] = g_dyn + A_SZ;
    smAl[0] = g_dyn + 2 * A_SZ;
    smAl[1] = g_dyn + 3 * A_SZ;
    smBh[0] = g_dyn + 4 * A_SZ;
    smBh[1] = g_dyn + 4 * A_SZ + B_SZ;
    smBl[0] = g_dyn + 4 * A_SZ + 2 * B_SZ;
    smBl[1] = g_dyn + 4 * A_SZ + 3 * B_SZ;

    const int tid  = threadIdx.x;
    const int warp = tid >> 5;
    const int lane = tid & 31;
    const int warp_m = warp & 1;
    const int warp_n = warp >> 1;
    const int m_base = warp_m * 64;
    const int n_base = warp_n * 32;

    const long long z = blockIdx.z;
    const __nv_bfloat16* Ahp = Ah + z * sA + (long long)blockIdx.y * 128 * K;
    const __nv_bfloat16* Alp = Al + z * sA + (long long)blockIdx.y * 128 * K;
    const __nv_bfloat16* Bhp = Bh + z * sB + blockIdx.x * 128;
    const __nv_bfloat16* Blp = Bl + z * sB + blockIdx.x * 128;

    const int ar0 = tid >> 1, ac0 = (tid & 1) * 16;
    const int br0 = tid >> 4, bc0 = (tid & 15) * 8;

    float acc[4][4][4];
    for (int a = 0; a < 4; a++)
        for (int b = 0; b < 4; b++)
            for (int c = 0; c < 4; c++)
                acc[a][b][c] = 0.f;

    const int lm_row = lane & 15;
    const int lm_col = (lane >> 4) * 8;
    const int nIter = K / 32;

    #define LOAD_STAGE(st, k0)                                                  \
    {                                                                           \
        long long ga = (long long)ar0 * K + (k0) + ac0;                         \
        cp16p(smAh[st] + ar0 * 40 + ac0,     Ahp + ga);                         \
        cp16p(smAh[st] + ar0 * 40 + ac0 + 8, Ahp + ga + 8);                     \
        cp16p(smAl[st] + ar0 * 40 + ac0,     Alp + ga);                         \
        cp16p(smAl[st] + ar0 * 40 + ac0 + 8, Alp + ga + 8);                     \
        long long gb0 = (long long)((k0) + br0) * N + bc0;                      \
        long long gb1 = (long long)((k0) + br0 + 16) * N + bc0;                 \
        cp16p(smBh[st] + br0 * 136 + bc0,        Bhp + gb0);                    \
        cp16p(smBh[st] + (br0 + 16) * 136 + bc0, Bhp + gb1);                    \
        cp16p(smBl[st] + br0 * 136 + bc0,        Blp + gb0);                    \
        cp16p(smBl[st] + (br0 + 16) * 136 + bc0, Blp + gb1);                    \
        cp_commit();                                                            \
    }

    LOAD_STAGE(0, 0);

    for (int it = 0; it < nIter; it++) {
        const int cur = it & 1;
        cp_wait<0>();
        __syncthreads();
        if (it + 1 < nIter) {
            LOAD_STAGE(cur ^ 1, (it + 1) * 32);
        }

        #pragma unroll
        for (int kk = 0; kk < 2; kk++) {
            const int ks = kk * 16;
            unsigned int ahf[4][4], alf[4][4], bhf[4][2], blf[4][2];
            #pragma unroll
            for (int mt = 0; mt < 4; mt++) {
                ldmat_x4(ahf[mt], smAh[cur] + (m_base + mt * 16 + lm_row) * 40 + ks + lm_col);
                ldmat_x4(alf[mt], smAl[cur] + (m_base + mt * 16 + lm_row) * 40 + ks + lm_col);
            }
            #pragma unroll
            for (int ng = 0; ng < 2; ng++) {
                unsigned int t[4];
                ldmat_x4t(t, smBh[cur] + (ks + lm_row) * 136 + n_base + ng * 16 + lm_col);
                bhf[2 * ng][0]     = t[0];
                bhf[2 * ng][1]     = t[1];
                bhf[2 * ng + 1][0] = t[2];
                bhf[2 * ng + 1][1] = t[3];
                ldmat_x4t(t, smBl[cur] + (ks + lm_row) * 136 + n_base + ng * 16 + lm_col);
                blf[2 * ng][0]     = t[0];
                blf[2 * ng][1]     = t[1];
                blf[2 * ng + 1][0] = t[2];
                blf[2 * ng + 1][1] = t[3];
            }
            // term-major: consecutive MMAs hit different accumulators
            #pragma unroll
            for (int mt = 0; mt < 4; mt++)
                #pragma unroll
                for (int nt = 0; nt < 4; nt++)
                    mma16816(acc[mt][nt], ahf[mt], bhf[nt]);
            #pragma unroll
            for (int mt = 0; mt < 4; mt++)
                #pragma unroll
                for (int nt = 0; nt < 4; nt++)
                    mma16816(acc[mt][nt], ahf[mt], blf[nt]);
            #pragma unroll
            for (int mt = 0; mt < 4; mt++)
                #pragma unroll
                for (int nt = 0; nt < 4; nt++)
                    mma16816(acc[mt][nt], alf[mt], bhf[nt]);
        }
    }

    // epilogue
    const int grp = lane >> 2;
    const int tq  = lane & 3;
    const long long crow0 = (long long)blockIdx.y * 128;
    const int ccol0 = blockIdx.x * 128;
    float* Cfp = Cf ? (Cf + z * sC) : (float*)0;
    __nv_bfloat16* Chp = Ch ? (Ch + z * sC) : (__nv_bfloat16*)0;
    __nv_bfloat16* Clp = Cl ? (Cl + z * sC) : (__nv_bfloat16*)0;

    for (int mt = 0; mt < 4; mt++) {
        for (int nt = 0; nt < 4; nt++) {
            int c = ccol0 + n_base + nt * 8 + 2 * tq;
            float b0 = bias ? bias[c] : 0.f;
            float b1 = bias ? bias[c + 1] : 0.f;
            for (int half = 0; half < 2; half++) {
                long long r = crow0 + m_base + mt * 16 + grp + half * 8;
                float v0 = acc[mt][nt][2 * half + 0] + b0;
                float v1 = acc[mt][nt][2 * half + 1] + b1;
                if (Cfp) {
                    float2 v;
                    v.x = v0; v.y = v1;
                    *(float2*)(Cfp + r * N + c) = v;
                }
                if (Chp) {
                    __nv_bfloat16 h0, h1, l0, l1;
                    split2(v0, h0, l0);
                    split2(v1, h1, l1);
                    __nv_bfloat162 p;
                    p.x = h0; p.y = h1;
                    *(__nv_bfloat162*)(Chp + r * N + c) = p;
                    p.x = l0; p.y = l1;
                    *(__nv_bfloat162*)(Clp + r * N + c) = p;
                }
            }
        }
    }
}

// ---------------------------------------------------------------------------
// fidelity kernel + interference + softmax -> attn (fp32) + bf16 hi/lo split
// ---------------------------------------------------------------------------
__global__ __launch_bounds__(256)
void attn_kernel(float* __restrict__ attn)
{
    int row = blockIdx.x;
    int b = row >> 9;
    int i = row & 511;
    const float* st_b = g_states + (size_t)b * S_ * (Q_ * 4);

    __shared__ float si[Q_ * 4];
    __shared__ float sK[S_];
    __shared__ float scp[S_];
    __shared__ float ssp[S_];
    __shared__ float red[8];

    if (threadIdx.x < Q_ * 4)
        si[threadIdx.x] = st_b[(size_t)i * (Q_ * 4) + threadIdx.x];
    for (int j = threadIdx.x; j < S_; j += 256) {
        scp[j] = g_cphi[j];
        ssp[j] = g_sphi[j];
    }
    __syncthreads();

    float ci  = scp[i];
    float sii = ssp[i];

    for (int j = threadIdx.x; j < S_; j += 256) {
        const float* sj = st_b + (size_t)j * (Q_ * 4);
        float Kv = 1.f;
        #pragma unroll
        for (int q = 0; q < Q_; q++) {
            float air = si[q * 4 + 0], aii = si[q * 4 + 1];
            float bir = si[q * 4 + 2], bii = si[q * 4 + 3];
            float ajr = sj[q * 4 + 0], aji = sj[q * 4 + 1];
            float bjr = sj[q * 4 + 2], bji = sj[q * 4 + 3];
            float re = air * ajr + aii * aji + bir * bjr + bii * bji;
            float im = air * aji - aii * ajr + bir * bji - bii * bjr;
            Kv *= re * re + im * im;
        }
        sK[j] = Kv + ci * scp[j] + sii * ssp[j];
    }
    __syncthreads();

    float m = -1e30f;
    for (int j = threadIdx.x; j < S_; j += 256)
        m = fmaxf(m, sK[j]);
    for (int off = 16; off; off >>= 1)
        m = fmaxf(m, __shfl_xor_sync(0xffffffffu, m, off));
    if ((threadIdx.x & 31) == 0)
        red[threadIdx.x >> 5] = m;
    __syncthreads();
    if (threadIdx.x < 8) {
        float v = red[threadIdx.x];
        for (int off = 4; off; off >>= 1)
            v = fmaxf(v, __shfl_xor_sync(0xffu, v, off));
        if (threadIdx.x == 0) red[0] = v;
    }
    __syncthreads();
    m = red[0];
    __syncthreads();

    float sum = 0.f;
    for (int j = threadIdx.x; j < S_; j += 256) {
        float e = expf(sK[j] - m);
        sK[j] = e;
        sum += e;
    }
    for (int off = 16; off; off >>= 1)
        sum += __shfl_xor_sync(0xffffffffu, sum, off);
    if ((threadIdx.x & 31) == 0)
        red[threadIdx.x >> 5] = sum;
    __syncthreads();
    if (threadIdx.x < 8) {
        float v = red[threadIdx.x];
        for (int off = 4; off; off >>= 1)
            v += __shfl_xor_sync(0xffu, v, off);
        if (threadIdx.x == 0) red[0] = v;
    }
    __syncthreads();
    float inv = 1.f / red[0];

    float* arow = attn + (size_t)row * S_;
    __nv_bfloat16* hrow = g_Ath + (size_t)row * S_;
    __nv_bfloat16* lrow = g_Atl + (size_t)row * S_;
    for (int j = threadIdx.x; j < S_; j += 256) {
        float v = sK[j] * inv;
        arow[j] = v;
        __nv_bfloat16 h, l;
        split2(v, h, l);
        hrow[j] = h;
        lrow[j] = l;
    }
}

// ---------------------------------------------------------------------------
// launch: weight branch on side stream overlaps X-side chain; join before
// the final GEMM. Streams/events created once; no device memory involved.
// ---------------------------------------------------------------------------
extern "C" void kernel_launch(void* const* d_in, const int* in_sizes, int n_in,
                              void* d_out, int out_size)
{
    const float* X     = (const float*)d_in[0];
    const float* Wq    = (const float*)d_in[1];
    const float* bq    = (const float*)d_in[2];
    const float* Wv    = (const float*)d_in[3];
    const float* bv    = (const float*)d_in[4];
    const float* Wo    = (const float*)d_in[5];
    const float* bo    = (const float*)d_in[6];
    const float* theta = (const float*)d_in[7];
    const float* phi   = (const float*)d_in[8];

    float* out  = (float*)d_out;
    float* attn = (float*)d_out + OUT_ELEMS;

    (void)in_sizes;
    (void)n_in;
    (void)out_size;

    __nv_bfloat16 *Xh, *Xl, *Wvh, *Wvl, *Woh, *Wol, *W2h, *W2l, *Ath, *Atl, *Uh, *Ul;
    float* b2;
    cudaGetSymbolAddress((void**)&Xh,  g_Xh);
    cudaGetSymbolAddress((void**)&Xl,  g_Xl);
    cudaGetSymbolAddress((void**)&Wvh, g_Wvh);
    cudaGetSymbolAddress((void**)&Wvl, g_Wvl);
    cudaGetSymbolAddress((void**)&Woh, g_Woh);
    cudaGetSymbolAddress((void**)&Wol, g_Wol);
    cudaGetSymbolAddress((void**)&W2h, g_W2h);
    cudaGetSymbolAddress((void**)&W2l, g_W2l);
    cudaGetSymbolAddress((void**)&Ath, g_Ath);
    cudaGetSymbolAddress((void**)&Atl, g_Atl);
    cudaGetSymbolAddress((void**)&Uh,  g_Uh);
    cudaGetSymbolAddress((void**)&Ul,  g_Ul);
    cudaGetSymbolAddress((void**)&b2,  g_b2);

    static cudaStream_t s1 = 0;
    static cudaEvent_t  evRoot = 0, evW2 = 0;
    static int s_init_done = 0;
    if (!s_init_done) {
        cudaFuncSetAttribute(gemm_bf16s,
                             cudaFuncAttributeMaxDynamicSharedMemorySize,
                             GEMM_SMEM_BYTES);
        cudaStreamCreateWithFlags(&s1, cudaStreamNonBlocking);
        cudaEventCreateWithFlags(&evRoot, cudaEventDisableTiming);
        cudaEventCreateWithFlags(&evW2,   cudaEventDisableTiming);
        s_init_done = 1;
    }

    // ---- fork: weight branch on s1 ----
    cudaEventRecord(evRoot, 0);
    cudaStreamWaitEvent(s1, evRoot, 0);

    split_fp32_kernel<<<(E_ * E_ / 4 + 255) / 256, 256, 0, s1>>>(Wv, Wvh, Wvl, E_ * E_);
    split_fp32_kernel<<<(E_ * E_ / 4 + 255) / 256, 256, 0, s1>>>(Wo, Woh, Wol, E_ * E_);
    {
        dim3 gp(E_ / 256, B2_KSPLIT);
        bias2_part_kernel<<<gp, 256, 0, s1>>>(bv, Wo);
        bias2_reduce_kernel<<<E_ / 256, 256, 0, s1>>>(bo);
    }
    {
        dim3 grid(E_ / 128, E_ / 128, 1);
        gemm_bf16s<<<grid, 256, GEMM_SMEM_BYTES, s1>>>(Wvh, Wvl, Woh, Wol, (const float*)0,
                                                       (float*)0, W2h, W2l,
                                                       E_, E_, E_, 0, 0, 0);
    }
    cudaEventRecord(evW2, s1);

    // ---- critical chain on the capture (default) stream ----
    phis_kernel<<<1, S_>>>(phi);
    qsplit_kernel<<<BS_ROWS / 8, 256>>>(X, Wq, bq, theta, Xh, Xl);
    attn_kernel<<<BS_ROWS, 256>>>(attn);
    {
        dim3 grid(E_ / 128, S_ / 128, B_);
        gemm_bf16s<<<grid, 256, GEMM_SMEM_BYTES>>>(Ath, Atl, Xh, Xl, (const float*)0,
                                                   (float*)0, Uh, Ul,
                                                   S_, E_, S_,
                                                   (long long)S_ * S_,
                                                   (long long)S_ * E_,
                                                   (long long)S_ * E_);
    }

    // ---- join: final GEMM needs W2 + b2 from s1 ----
    cudaStreamWaitEvent(0, evW2, 0);
    {
        dim3 grid(E_ / 128, BS_ROWS / 128, 1);
        gemm_bf16s<<<grid, 256, GEMM_SMEM_BYTES>>>(Uh, Ul, W2h, W2l, b2,
                                                   out, (__nv_bfloat16*)0, (__nv_bfloat16*)0,
                                                   BS_ROWS, E_, E_, 0, 0, 0);
    }
}

// round 12
// speedup vs baseline: 1.2955x; 1.2955x over previous
#include <cuda_runtime.h>
#include <cuda_bf16.h>
#include <stdint.h>
#include <math.h>

// Problem shapes (fixed per reference)
#define B_ 16
#define S_ 512
#define E_ 1024
#define Q_ 8
#define L_ 4

#define BS_ROWS (B_ * S_)            // 8192
#define OUT_ELEMS (B_ * S_ * E_)     // 8388608

#define B2_KSPLIT 32                 // k-chunks for bias2

// ---------------------------------------------------------------------------
// Scratch (device globals: allocation-free rule). 16B-aligned for uint4 I/O.
// ---------------------------------------------------------------------------
__device__ __align__(16) float g_states[BS_ROWS * Q_ * 4];
__device__ __align__(16) float g_cphi[S_];
__device__ __align__(16) float g_sphi[S_];
__device__ __align__(16) float g_b2[E_];                  // bv@Wo + bo
__device__ __align__(16) float g_b2p[B2_KSPLIT * E_];     // partials

__device__ __align__(16) __nv_bfloat16 g_Xh[BS_ROWS * E_];
__device__ __align__(16) __nv_bfloat16 g_Xl[BS_ROWS * E_];
__device__ __align__(16) __nv_bfloat16 g_Wvh[E_ * E_];
__device__ __align__(16) __nv_bfloat16 g_Wvl[E_ * E_];
__device__ __align__(16) __nv_bfloat16 g_Woh[E_ * E_];
__device__ __align__(16) __nv_bfloat16 g_Wol[E_ * E_];
__device__ __align__(16) __nv_bfloat16 g_W2h[E_ * E_];    // (Wv@Wo) split
__device__ __align__(16) __nv_bfloat16 g_W2l[E_ * E_];
__device__ __align__(16) __nv_bfloat16 g_Ath[B_ * S_ * S_];
__device__ __align__(16) __nv_bfloat16 g_Atl[B_ * S_ * S_];
__device__ __align__(16) __nv_bfloat16 g_Uh[BS_ROWS * E_];  // (attn@X) split
__device__ __align__(16) __nv_bfloat16 g_Ul[BS_ROWS * E_];

__device__ __forceinline__ void split2(float v, __nv_bfloat16 &h, __nv_bfloat16 &l)
{
    h = __float2bfloat16(v);
    l = __float2bfloat16(v - __bfloat162float(h));
}

// ---------------------------------------------------------------------------
// Split fp32 -> bf16 hi/lo (vectorized) — for Wv, Wo
// ---------------------------------------------------------------------------
__global__ void split_fp32_kernel(const float* __restrict__ src,
                                  __nv_bfloat16* __restrict__ h,
                                  __nv_bfloat16* __restrict__ l, int n)
{
    int i = (blockIdx.x * blockDim.x + threadIdx.x) * 4;
    if (i >= n) return;
    float4 v = *(const float4*)(src + i);
    __nv_bfloat16 h0, h1, h2, h3, l0, l1, l2, l3;
    split2(v.x, h0, l0);
    split2(v.y, h1, l1);
    split2(v.z, h2, l2);
    split2(v.w, h3, l3);
    __nv_bfloat162 p;
    p.x = h0; p.y = h1; *(__nv_bfloat162*)(h + i)     = p;
    p.x = h2; p.y = h3; *(__nv_bfloat162*)(h + i + 2) = p;
    p.x = l0; p.y = l1; *(__nv_bfloat162*)(l + i)     = p;
    p.x = l2; p.y = l3; *(__nv_bfloat162*)(l + i + 2) = p;
}

// ---------------------------------------------------------------------------
// Precompute cos(phi)/sin(phi); b2 = bv@Wo + bo in two phases
// ---------------------------------------------------------------------------
__global__ void phis_kernel(const float* __restrict__ phi)
{
    int j = threadIdx.x;
    float p = phi[j];
    g_cphi[j] = cosf(p);
    g_sphi[j] = sinf(p);
}

__global__ void bias2_part_kernel(const float* __restrict__ bv,
                                  const float* __restrict__ Wo)
{
    int n  = blockIdx.x * 256 + threadIdx.x;
    int k0 = blockIdx.y * (E_ / B2_KSPLIT);
    float acc = 0.f;
    #pragma unroll 4
    for (int k = k0; k < k0 + E_ / B2_KSPLIT; k++)
        acc += bv[k] * Wo[(size_t)k * E_ + n];
    g_b2p[blockIdx.y * E_ + n] = acc;
}

__global__ void bias2_reduce_kernel(const float* __restrict__ bo)
{
    int n = blockIdx.x * 256 + threadIdx.x;
    float acc = bo[n];
    #pragma unroll
    for (int ky = 0; ky < B2_KSPLIT; ky++)
        acc += g_b2p[ky * E_ + n];
    g_b2[n] = acc;
}

// ---------------------------------------------------------------------------
// Kernel 1: fused X split + quantum_input + qubit recursion (vectorized)
// ---------------------------------------------------------------------------
__global__ __launch_bounds__(256)
void qsplit_kernel(const float* __restrict__ X,
                   const float* __restrict__ Wq,
                   const float* __restrict__ bq,
                   const float* __restrict__ theta,
                   __nv_bfloat16* __restrict__ Xh,
                   __nv_bfloat16* __restrict__ Xl)
{
    __shared__ float sWq[Q_][E_];

    const int tid  = threadIdx.x;
    const int warp = tid >> 5;
    const int lane = tid & 31;

    for (int idx = tid; idx < E_ * Q_; idx += 256) {
        int e = idx >> 3;
        int q = idx & 7;
        sWq[q][e] = Wq[idx];
    }
    __syncthreads();

    const int row = blockIdx.x * 8 + warp;
    const float* x = X + (size_t)row * E_;
    __nv_bfloat16* xh = Xh + (size_t)row * E_;
    __nv_bfloat16* xl = Xl + (size_t)row * E_;

    float acc[Q_];
    #pragma unroll
    for (int q = 0; q < Q_; q++) acc[q] = 0.f;

    for (int e0 = lane * 4; e0 < E_; e0 += 128) {
        float4 xv = *(const float4*)(x + e0);
        __nv_bfloat16 h0, h1, h2, h3, l0, l1, l2, l3;
        split2(xv.x, h0, l0);
        split2(xv.y, h1, l1);
        split2(xv.z, h2, l2);
        split2(xv.w, h3, l3);
        __nv_bfloat162 p;
        p.x = h0; p.y = h1; *(__nv_bfloat162*)(xh + e0)     = p;
        p.x = h2; p.y = h3; *(__nv_bfloat162*)(xh + e0 + 2) = p;
        p.x = l0; p.y = l1; *(__nv_bfloat162*)(xl + e0)     = p;
        p.x = l2; p.y = l3; *(__nv_bfloat162*)(xl + e0 + 2) = p;
        #pragma unroll
        for (int q = 0; q < Q_; q++) {
            float4 w = *(const float4*)&sWq[q][e0];
            acc[q] += xv.x * w.x + xv.y * w.y + xv.z * w.z + xv.w * w.w;
        }
    }
    #pragma unroll
    for (int q = 0; q < Q_; q++)
        for (int off = 16; off; off >>= 1)
            acc[q] += __shfl_xor_sync(0xffffffffu, acc[q], off);

    if (lane < Q_) {
        int q = lane;
        float ang = acc[q] + bq[q];
        float ar = cosf(0.5f * ang);
        float ai = 0.f;
        float br = sinf(0.5f * ang);
        float bi = 0.f;
        for (int l = 0; l < L_; l++) {
            float t0 = 0.5f * theta[(l * Q_ + q) * 2 + 0];
            float t1 = 0.5f * theta[(l * Q_ + q) * 2 + 1];
            float c = cosf(t0), s = sinf(t0);
            float nar = c * ar - s * br, nai = c * ai - s * bi;
            float nbr = s * ar + c * br, nbi = s * ai + c * bi;
            float cp = cosf(t1), sp = sinf(t1);
            ar = nar * cp + nai * sp;
            ai = nai * cp - nar * sp;
            br = nbr * cp - nbi * sp;
            bi = nbi * cp + nbr * sp;
        }
        float* st = g_states + (size_t)row * (Q_ * 4) + q * 4;
        st[0] = ar; st[1] = ai; st[2] = br; st[3] = bi;
    }
}

// ---------------------------------------------------------------------------
// mma.sync / cp.async helpers
// ---------------------------------------------------------------------------
__device__ __forceinline__ void ldmat_x4(unsigned int* r, const __nv_bfloat16* p)
{
    unsigned int a = (unsigned int)__cvta_generic_to_shared(p);
    asm volatile("ldmatrix.sync.aligned.m8n8.x4.shared.b16 {%0,%1,%2,%3}, [%4];"
                 : "=r"(r[0]), "=r"(r[1]), "=r"(r[2]), "=r"(r[3]) : "r"(a));
}
__device__ __forceinline__ void ldmat_x4t(unsigned int* r, const __nv_bfloat16* p)
{
    unsigned int a = (unsigned int)__cvta_generic_to_shared(p);
    asm volatile("ldmatrix.sync.aligned.m8n8.x4.trans.shared.b16 {%0,%1,%2,%3}, [%4];"
                 : "=r"(r[0]), "=r"(r[1]), "=r"(r[2]), "=r"(r[3]) : "r"(a));
}
__device__ __forceinline__ void mma16816(float* d, const unsigned int* a, const unsigned int* b)
{
    asm volatile(
        "mma.sync.aligned.m16n8k16.row.col.f32.bf16.bf16.f32 "
        "{%0,%1,%2,%3}, {%4,%5,%6,%7}, {%8,%9}, {%0,%1,%2,%3};"
        : "+f"(d[0]), "+f"(d[1]), "+f"(d[2]), "+f"(d[3])
        : "r"(a[0]), "r"(a[1]), "r"(a[2]), "r"(a[3]), "r"(b[0]), "r"(b[1]));
}
__device__ __forceinline__ void cp16p(__nv_bfloat16* dst, const __nv_bfloat16* src)
{
    unsigned int d = (unsigned int)__cvta_generic_to_shared(dst);
    asm volatile("cp.async.cg.shared.global [%0], [%1], 16;" :: "r"(d), "l"(src));
}
__device__ __forceinline__ void cp_commit()
{
    asm volatile("cp.async.commit_group;");
}
template <int N>
__device__ __forceinline__ void cp_wait()
{
    asm volatile("cp.async.wait_group %0;" :: "n"(N));
}

// ---------------------------------------------------------------------------
// bf16-split GEMM, cp.async double-buffered, term-major MMA ordering.
// C = (Ah+Al)(Bh+Bl) ~= AhBh + AhBl + AlBh
// A row-major [M,K], B row-major [K,N]. 128x128x32 tile, 256 thr (8 warps).
// ---------------------------------------------------------------------------
#define A_SZ (128 * 40)
#define B_SZ (32 * 136)
#define GEMM_SMEM_BYTES ((4 * A_SZ + 4 * B_SZ) * 2)

extern __shared__ __nv_bfloat16 g_dyn[];

__global__ __launch_bounds__(256)
void gemm_bf16s(const __nv_bfloat16* __restrict__ Ah, const __nv_bfloat16* __restrict__ Al,
                const __nv_bfloat16* __restrict__ Bh, const __nv_bfloat16* __restrict__ Bl,
                const float* __restrict__ bias,
                float* __restrict__ Cf,
                __nv_bfloat16* __restrict__ Ch, __nv_bfloat16* __restrict__ Cl,
                int M, int N, int K,
                long long sA, long long sB, long long sC)
{
    __nv_bfloat16* smAh[2];
    __nv_bfloat16* smAl[2];
    __nv_bfloat16* smBh[2];
    __nv_bfloat16* smBl[2];
    smAh[0] = g_dyn;
    smAh[1] = g_dyn + A_SZ;
    smAl[0] = g_dyn + 2 * A_SZ;
    smAl[1] = g_dyn + 3 * A_SZ;
    smBh[0] = g_dyn + 4 * A_SZ;
    smBh[1] = g_dyn + 4 * A_SZ + B_SZ;
    smBl[0] = g_dyn + 4 * A_SZ + 2 * B_SZ;
    smBl[1] = g_dyn + 4 * A_SZ + 3 * B_SZ;

    const int tid  = threadIdx.x;
    const int warp = tid >> 5;
    const int lane = tid & 31;
    const int warp_m = warp & 1;
    const int warp_n = warp >> 1;
    const int m_base = warp_m * 64;
    const int n_base = warp_n * 32;

    const long long z = blockIdx.z;
    const __nv_bfloat16* Ahp = Ah + z * sA + (long long)blockIdx.y * 128 * K;
    const __nv_bfloat16* Alp = Al + z * sA + (long long)blockIdx.y * 128 * K;
    const __nv_bfloat16* Bhp = Bh + z * sB + blockIdx.x * 128;
    const __nv_bfloat16* Blp = Bl + z * sB + blockIdx.x * 128;

    const int ar0 = tid >> 1, ac0 = (tid & 1) * 16;
    const int br0 = tid >> 4, bc0 = (tid & 15) * 8;

    float acc[4][4][4];
    for (int a = 0; a < 4; a++)
        for (int b = 0; b < 4; b++)
            for (int c = 0; c < 4; c++)
                acc[a][b][c] = 0.f;

    const int lm_row = lane & 15;
    const int lm_col = (lane >> 4) * 8;
    const int nIter = K / 32;

    #define LOAD_STAGE(st, k0)                                                  \
    {                                                                           \
        long long ga = (long long)ar0 * K + (k0) + ac0;                         \
        cp16p(smAh[st] + ar0 * 40 + ac0,     Ahp + ga);                         \
        cp16p(smAh[st] + ar0 * 40 + ac0 + 8, Ahp + ga + 8);                     \
        cp16p(smAl[st] + ar0 * 40 + ac0,     Alp + ga);                         \
        cp16p(smAl[st] + ar0 * 40 + ac0 + 8, Alp + ga + 8);                     \
        long long gb0 = (long long)((k0) + br0) * N + bc0;                      \
        long long gb1 = (long long)((k0) + br0 + 16) * N + bc0;                 \
        cp16p(smBh[st] + br0 * 136 + bc0,        Bhp + gb0);                    \
        cp16p(smBh[st] + (br0 + 16) * 136 + bc0, Bhp + gb1);                    \
        cp16p(smBl[st] + br0 * 136 + bc0,        Blp + gb0);                    \
        cp16p(smBl[st] + (br0 + 16) * 136 + bc0, Blp + gb1);                    \
        cp_commit();                                                            \
    }

    LOAD_STAGE(0, 0);

    for (int it = 0; it < nIter; it++) {
        const int cur = it & 1;
        cp_wait<0>();
        __syncthreads();
        if (it + 1 < nIter) {
            LOAD_STAGE(cur ^ 1, (it + 1) * 32);
        }

        #pragma unroll
        for (int kk = 0; kk < 2; kk++) {
            const int ks = kk * 16;
            unsigned int ahf[4][4], alf[4][4], bhf[4][2], blf[4][2];
            #pragma unroll
            for (int mt = 0; mt < 4; mt++) {
                ldmat_x4(ahf[mt], smAh[cur] + (m_base + mt * 16 + lm_row) * 40 + ks + lm_col);
                ldmat_x4(alf[mt], smAl[cur] + (m_base + mt * 16 + lm_row) * 40 + ks + lm_col);
            }
            #pragma unroll
            for (int ng = 0; ng < 2; ng++) {
                unsigned int t[4];
                ldmat_x4t(t, smBh[cur] + (ks + lm_row) * 136 + n_base + ng * 16 + lm_col);
                bhf[2 * ng][0]     = t[0];
                bhf[2 * ng][1]     = t[1];
                bhf[2 * ng + 1][0] = t[2];
                bhf[2 * ng + 1][1] = t[3];
                ldmat_x4t(t, smBl[cur] + (ks + lm_row) * 136 + n_base + ng * 16 + lm_col);
                blf[2 * ng][0]     = t[0];
                blf[2 * ng][1]     = t[1];
                blf[2 * ng + 1][0] = t[2];
                blf[2 * ng + 1][1] = t[3];
            }
            #pragma unroll
            for (int mt = 0; mt < 4; mt++)
                #pragma unroll
                for (int nt = 0; nt < 4; nt++)
                    mma16816(acc[mt][nt], ahf[mt], bhf[nt]);
            #pragma unroll
            for (int mt = 0; mt < 4; mt++)
                #pragma unroll
                for (int nt = 0; nt < 4; nt++)
                    mma16816(acc[mt][nt], ahf[mt], blf[nt]);
            #pragma unroll
            for (int mt = 0; mt < 4; mt++)
                #pragma unroll
                for (int nt = 0; nt < 4; nt++)
                    mma16816(acc[mt][nt], alf[mt], bhf[nt]);
        }
    }

    // epilogue
    const int grp = lane >> 2;
    const int tq  = lane & 3;
    const long long crow0 = (long long)blockIdx.y * 128;
    const int ccol0 = blockIdx.x * 128;
    float* Cfp = Cf ? (Cf + z * sC) : (float*)0;
    __nv_bfloat16* Chp = Ch ? (Ch + z * sC) : (__nv_bfloat16*)0;
    __nv_bfloat16* Clp = Cl ? (Cl + z * sC) : (__nv_bfloat16*)0;

    for (int mt = 0; mt < 4; mt++) {
        for (int nt = 0; nt < 4; nt++) {
            int c = ccol0 + n_base + nt * 8 + 2 * tq;
            float b0 = bias ? bias[c] : 0.f;
            float b1 = bias ? bias[c + 1] : 0.f;
            for (int half = 0; half < 2; half++) {
                long long r = crow0 + m_base + mt * 16 + grp + half * 8;
                float v0 = acc[mt][nt][2 * half + 0] + b0;
                float v1 = acc[mt][nt][2 * half + 1] + b1;
                if (Cfp) {
                    float2 v;
                    v.x = v0; v.y = v1;
                    *(float2*)(Cfp + r * N + c) = v;
                }
                if (Chp) {
                    __nv_bfloat16 h0, h1, l0, l1;
                    split2(v0, h0, l0);
                    split2(v1, h1, l1);
                    __nv_bfloat162 p;
                    p.x = h0; p.y = h1;
                    *(__nv_bfloat162*)(Chp + r * N + c) = p;
                    p.x = l0; p.y = l1;
                    *(__nv_bfloat162*)(Clp + r * N + c) = p;
                }
            }
        }
    }
}

// ---------------------------------------------------------------------------
// attn v2: warp-per-row, 8 rows/block, batch states cached in padded smem,
// register-resident j-tile, warp-shuffle softmax, __expf.
// grid = BS_ROWS/8 = 1024, 256 threads.
// ---------------------------------------------------------------------------
#define SROW 33                               // padded floats per state row
#define ATTN_SMEM_BYTES ((S_ * SROW + 2 * S_) * 4)   // 67584 + 4096 = 71680

__global__ __launch_bounds__(256)
void attn_kernel(float* __restrict__ attn)
{
    float* sst = (float*)g_dyn;               // [S_][SROW]
    float* scp = sst + S_ * SROW;             // [S_]
    float* ssp = scp + S_;                    // [S_]

    const int tid  = threadIdx.x;
    const int warp = tid >> 5;
    const int lane = tid & 31;

    const int blk = blockIdx.x;
    const int b   = blk >> 6;                 // 64 blocks per batch
    const int i0  = (blk & 63) * 8;
    const float* st_b = g_states + (size_t)b * S_ * 32;

    // load batch states (512 rows x 32 floats) into padded smem
    for (int idx = tid; idx < S_ * 8; idx += 256) {
        int row = idx >> 3;
        int c4  = (idx & 7) * 4;
        float4 v = *(const float4*)(st_b + row * 32 + c4);
        float* d = sst + row * SROW + c4;
        d[0] = v.x; d[1] = v.y; d[2] = v.z; d[3] = v.w;
    }
    for (int j = tid; j < S_; j += 256) {
        scp[j] = g_cphi[j];
        ssp[j] = g_sphi[j];
    }
    __syncthreads();

    const int i = i0 + warp;

    float si[32];
    #pragma unroll
    for (int k = 0; k < 32; k++)
        si[k] = sst[i * SROW + k];            // broadcast read
    const float ci  = scp[i];
    const float sii = ssp[i];

    float Kv[16];
    float m = -1e30f;
    #pragma unroll
    for (int jj = 0; jj < 16; jj++) {
        const int j = lane + jj * 32;
        const float* sj = sst + j * SROW;     // conflict-free: (j*33+k)%32 distinct per lane
        float p = 1.f;
        #pragma unroll
        for (int q = 0; q < Q_; q++) {
            float air = si[q * 4 + 0], aii = si[q * 4 + 1];
            float bir = si[q * 4 + 2], bii = si[q * 4 + 3];
            float ajr = sj[q * 4 + 0], aji = sj[q * 4 + 1];
            float bjr = sj[q * 4 + 2], bji = sj[q * 4 + 3];
            float re = air * ajr + aii * aji + bir * bjr + bii * bji;
            float im = air * aji - aii * ajr + bir * bji - bii * bjr;
            p *= re * re + im * im;
        }
        float v = p + ci * scp[j] + sii * ssp[j];
        Kv[jj] = v;
        m = fmaxf(m, v);
    }
    #pragma unroll
    for (int off = 16; off; off >>= 1)
        m = fmaxf(m, __shfl_xor_sync(0xffffffffu, m, off));

    float sum = 0.f;
    #pragma unroll
    for (int jj = 0; jj < 16; jj++) {
        float e = __expf(Kv[jj] - m);
        Kv[jj] = e;
        sum += e;
    }
    #pragma unroll
    for (int off = 16; off; off >>= 1)
        sum += __shfl_xor_sync(0xffffffffu, sum, off);
    const float inv = 1.f / sum;

    const size_t row = (size_t)b * S_ + i;
    float* arow = attn + row * S_;
    __nv_bfloat16* hrow = g_Ath + row * S_;
    __nv_bfloat16* lrow = g_Atl + row * S_;
    #pragma unroll
    for (int jj = 0; jj < 16; jj++) {
        const int j = lane + jj * 32;
        float v = Kv[jj] * inv;
        arow[j] = v;
        __nv_bfloat16 h, l;
        split2(v, h, l);
        hrow[j] = h;
        lrow[j] = l;
    }
}

// ---------------------------------------------------------------------------
// launch: weight branch on side stream overlaps X-side chain; join before
// the final GEMM. Streams/events created once; no device memory involved.
// ---------------------------------------------------------------------------
extern "C" void kernel_launch(void* const* d_in, const int* in_sizes, int n_in,
                              void* d_out, int out_size)
{
    const float* X     = (const float*)d_in[0];
    const float* Wq    = (const float*)d_in[1];
    const float* bq    = (const float*)d_in[2];
    const float* Wv    = (const float*)d_in[3];
    const float* bv    = (const float*)d_in[4];
    const float* Wo    = (const float*)d_in[5];
    const float* bo    = (const float*)d_in[6];
    const float* theta = (const float*)d_in[7];
    const float* phi   = (const float*)d_in[8];

    float* out  = (float*)d_out;
    float* attn = (float*)d_out + OUT_ELEMS;

    (void)in_sizes;
    (void)n_in;
    (void)out_size;

    __nv_bfloat16 *Xh, *Xl, *Wvh, *Wvl, *Woh, *Wol, *W2h, *W2l, *Ath, *Atl, *Uh, *Ul;
    float* b2;
    cudaGetSymbolAddress((void**)&Xh,  g_Xh);
    cudaGetSymbolAddress((void**)&Xl,  g_Xl);
    cudaGetSymbolAddress((void**)&Wvh, g_Wvh);
    cudaGetSymbolAddress((void**)&Wvl, g_Wvl);
    cudaGetSymbolAddress((void**)&Woh, g_Woh);
    cudaGetSymbolAddress((void**)&Wol, g_Wol);
    cudaGetSymbolAddress((void**)&W2h, g_W2h);
    cudaGetSymbolAddress((void**)&W2l, g_W2l);
    cudaGetSymbolAddress((void**)&Ath, g_Ath);
    cudaGetSymbolAddress((void**)&Atl, g_Atl);
    cudaGetSymbolAddress((void**)&Uh,  g_Uh);
    cudaGetSymbolAddress((void**)&Ul,  g_Ul);
    cudaGetSymbolAddress((void**)&b2,  g_b2);

    static cudaStream_t s1 = 0;
    static cudaEvent_t  evRoot = 0, evW2 = 0;
    static int s_init_done = 0;
    if (!s_init_done) {
        cudaFuncSetAttribute(gemm_bf16s,
                             cudaFuncAttributeMaxDynamicSharedMemorySize,
                             GEMM_SMEM_BYTES);
        cudaFuncSetAttribute(attn_kernel,
                             cudaFuncAttributeMaxDynamicSharedMemorySize,
                             ATTN_SMEM_BYTES);
        cudaStreamCreateWithFlags(&s1, cudaStreamNonBlocking);
        cudaEventCreateWithFlags(&evRoot, cudaEventDisableTiming);
        cudaEventCreateWithFlags(&evW2,   cudaEventDisableTiming);
        s_init_done = 1;
    }

    // ---- fork: weight branch on s1 ----
    cudaEventRecord(evRoot, 0);
    cudaStreamWaitEvent(s1, evRoot, 0);

    split_fp32_kernel<<<(E_ * E_ / 4 + 255) / 256, 256, 0, s1>>>(Wv, Wvh, Wvl, E_ * E_);
    split_fp32_kernel<<<(E_ * E_ / 4 + 255) / 256, 256, 0, s1>>>(Wo, Woh, Wol, E_ * E_);
    {
        dim3 gp(E_ / 256, B2_KSPLIT);
        bias2_part_kernel<<<gp, 256, 0, s1>>>(bv, Wo);
        bias2_reduce_kernel<<<E_ / 256, 256, 0, s1>>>(bo);
    }
    {
        dim3 grid(E_ / 128, E_ / 128, 1);
        gemm_bf16s<<<grid, 256, GEMM_SMEM_BYTES, s1>>>(Wvh, Wvl, Woh, Wol, (const float*)0,
                                                       (float*)0, W2h, W2l,
                                                       E_, E_, E_, 0, 0, 0);
    }
    cudaEventRecord(evW2, s1);

    // ---- critical chain on the capture (default) stream ----
    phis_kernel<<<1, S_>>>(phi);
    qsplit_kernel<<<BS_ROWS / 8, 256>>>(X, Wq, bq, theta, Xh, Xl);
    attn_kernel<<<BS_ROWS / 8, 256, ATTN_SMEM_BYTES>>>(attn);
    {
        dim3 grid(E_ / 128, S_ / 128, B_);
        gemm_bf16s<<<grid, 256, GEMM_SMEM_BYTES>>>(Ath, Atl, Xh, Xl, (const float*)0,
                                                   (float*)0, Uh, Ul,
                                                   S_, E_, S_,
                                                   (long long)S_ * S_,
                                                   (long long)S_ * E_,
                                                   (long long)S_ * E_);
    }

    // ---- join: final GEMM needs W2 + b2 from s1 ----
    cudaStreamWaitEvent(0, evW2, 0);
    {
        dim3 grid(E_ / 128, BS_ROWS / 128, 1);
        gemm_bf16s<<<grid, 256, GEMM_SMEM_BYTES>>>(Uh, Ul, W2h, W2l, b2,
                                                   out, (__nv_bfloat16*)0, (__nv_bfloat16*)0,
                                                   BS_ROWS, E_, E_, 0, 0, 0);
    }
}

// round 13
// speedup vs baseline: 1.3674x; 1.0555x over previous
#include <cuda_runtime.h>
#include <cuda_bf16.h>
#include <stdint.h>
#include <math.h>

// Problem shapes (fixed per reference)
#define B_ 16
#define S_ 512
#define E_ 1024
#define Q_ 8
#define L_ 4

#define BS_ROWS (B_ * S_)            // 8192
#define OUT_ELEMS (B_ * S_ * E_)     // 8388608

#define B2_KSPLIT 32                 // k-chunks for bias2
#define HALF_B (B_ / 2)              // 8 batches per chunk

// ---------------------------------------------------------------------------
// Scratch (device globals: allocation-free rule). 16B-aligned for uint4 I/O.
// ---------------------------------------------------------------------------
__device__ __align__(16) float g_states[BS_ROWS * Q_ * 4];
__device__ __align__(16) float g_cphi[S_];
__device__ __align__(16) float g_sphi[S_];
__device__ __align__(16) float g_b2[E_];                  // bv@Wo + bo
__device__ __align__(16) float g_b2p[B2_KSPLIT * E_];     // partials

__device__ __align__(16) __nv_bfloat16 g_Xh[BS_ROWS * E_];
__device__ __align__(16) __nv_bfloat16 g_Xl[BS_ROWS * E_];
__device__ __align__(16) __nv_bfloat16 g_Wvh[E_ * E_];
__device__ __align__(16) __nv_bfloat16 g_Wvl[E_ * E_];
__device__ __align__(16) __nv_bfloat16 g_Woh[E_ * E_];
__device__ __align__(16) __nv_bfloat16 g_Wol[E_ * E_];
__device__ __align__(16) __nv_bfloat16 g_W2h[E_ * E_];    // (Wv@Wo) split
__device__ __align__(16) __nv_bfloat16 g_W2l[E_ * E_];
__device__ __align__(16) __nv_bfloat16 g_Ath[B_ * S_ * S_];
__device__ __align__(16) __nv_bfloat16 g_Atl[B_ * S_ * S_];
__device__ __align__(16) __nv_bfloat16 g_Uh[BS_ROWS * E_];  // (attn@X) split
__device__ __align__(16) __nv_bfloat16 g_Ul[BS_ROWS * E_];

__device__ __forceinline__ void split2(float v, __nv_bfloat16 &h, __nv_bfloat16 &l)
{
    h = __float2bfloat16(v);
    l = __float2bfloat16(v - __bfloat162float(h));
}

// ---------------------------------------------------------------------------
// Split fp32 -> bf16 hi/lo (vectorized) — for Wv, Wo
// ---------------------------------------------------------------------------
__global__ void split_fp32_kernel(const float* __restrict__ src,
                                  __nv_bfloat16* __restrict__ h,
                                  __nv_bfloat16* __restrict__ l, int n)
{
    int i = (blockIdx.x * blockDim.x + threadIdx.x) * 4;
    if (i >= n) return;
    float4 v = *(const float4*)(src + i);
    __nv_bfloat16 h0, h1, h2, h3, l0, l1, l2, l3;
    split2(v.x, h0, l0);
    split2(v.y, h1, l1);
    split2(v.z, h2, l2);
    split2(v.w, h3, l3);
    __nv_bfloat162 p;
    p.x = h0; p.y = h1; *(__nv_bfloat162*)(h + i)     = p;
    p.x = h2; p.y = h3; *(__nv_bfloat162*)(h + i + 2) = p;
    p.x = l0; p.y = l1; *(__nv_bfloat162*)(l + i)     = p;
    p.x = l2; p.y = l3; *(__nv_bfloat162*)(l + i + 2) = p;
}

// ---------------------------------------------------------------------------
// Precompute cos(phi)/sin(phi); b2 = bv@Wo + bo in two phases
// ---------------------------------------------------------------------------
__global__ void phis_kernel(const float* __restrict__ phi)
{
    int j = threadIdx.x;
    float p = phi[j];
    g_cphi[j] = cosf(p);
    g_sphi[j] = sinf(p);
}

__global__ void bias2_part_kernel(const float* __restrict__ bv,
                                  const float* __restrict__ Wo)
{
    int n  = blockIdx.x * 256 + threadIdx.x;
    int k0 = blockIdx.y * (E_ / B2_KSPLIT);
    float acc = 0.f;
    #pragma unroll 4
    for (int k = k0; k < k0 + E_ / B2_KSPLIT; k++)
        acc += bv[k] * Wo[(size_t)k * E_ + n];
    g_b2p[blockIdx.y * E_ + n] = acc;
}

__global__ void bias2_reduce_kernel(const float* __restrict__ bo)
{
    int n = blockIdx.x * 256 + threadIdx.x;
    float acc = bo[n];
    #pragma unroll
    for (int ky = 0; ky < B2_KSPLIT; ky++)
        acc += g_b2p[ky * E_ + n];
    g_b2[n] = acc;
}

// ---------------------------------------------------------------------------
// Kernel 1: fused X split + quantum_input + qubit recursion (vectorized).
// row0 = starting row of this chunk.
// ---------------------------------------------------------------------------
__global__ __launch_bounds__(256)
void qsplit_kernel(const float* __restrict__ X,
                   const float* __restrict__ Wq,
                   const float* __restrict__ bq,
                   const float* __restrict__ theta,
                   __nv_bfloat16* __restrict__ Xh,
                   __nv_bfloat16* __restrict__ Xl,
                   int row0)
{
    __shared__ float sWq[Q_][E_];

    const int tid  = threadIdx.x;
    const int warp = tid >> 5;
    const int lane = tid & 31;

    for (int idx = tid; idx < E_ * Q_; idx += 256) {
        int e = idx >> 3;
        int q = idx & 7;
        sWq[q][e] = Wq[idx];
    }
    __syncthreads();

    const int row = row0 + blockIdx.x * 8 + warp;
    const float* x = X + (size_t)row * E_;
    __nv_bfloat16* xh = Xh + (size_t)row * E_;
    __nv_bfloat16* xl = Xl + (size_t)row * E_;

    float acc[Q_];
    #pragma unroll
    for (int q = 0; q < Q_; q++) acc[q] = 0.f;

    for (int e0 = lane * 4; e0 < E_; e0 += 128) {
        float4 xv = *(const float4*)(x + e0);
        __nv_bfloat16 h0, h1, h2, h3, l0, l1, l2, l3;
        split2(xv.x, h0, l0);
        split2(xv.y, h1, l1);
        split2(xv.z, h2, l2);
        split2(xv.w, h3, l3);
        __nv_bfloat162 p;
        p.x = h0; p.y = h1; *(__nv_bfloat162*)(xh + e0)     = p;
        p.x = h2; p.y = h3; *(__nv_bfloat162*)(xh + e0 + 2) = p;
        p.x = l0; p.y = l1; *(__nv_bfloat162*)(xl + e0)     = p;
        p.x = l2; p.y = l3; *(__nv_bfloat162*)(xl + e0 + 2) = p;
        #pragma unroll
        for (int q = 0; q < Q_; q++) {
            float4 w = *(const float4*)&sWq[q][e0];
            acc[q] += xv.x * w.x + xv.y * w.y + xv.z * w.z + xv.w * w.w;
        }
    }
    #pragma unroll
    for (int q = 0; q < Q_; q++)
        for (int off = 16; off; off >>= 1)
            acc[q] += __shfl_xor_sync(0xffffffffu, acc[q], off);

    if (lane < Q_) {
        int q = lane;
        float ang = acc[q] + bq[q];
        float ar = cosf(0.5f * ang);
        float ai = 0.f;
        float br = sinf(0.5f * ang);
        float bi = 0.f;
        for (int l = 0; l < L_; l++) {
            float t0 = 0.5f * theta[(l * Q_ + q) * 2 + 0];
            float t1 = 0.5f * theta[(l * Q_ + q) * 2 + 1];
            float c = cosf(t0), s = sinf(t0);
            float nar = c * ar - s * br, nai = c * ai - s * bi;
            float nbr = s * ar + c * br, nbi = s * ai + c * bi;
            float cp = cosf(t1), sp = sinf(t1);
            ar = nar * cp + nai * sp;
            ai = nai * cp - nar * sp;
            br = nbr * cp - nbi * sp;
            bi = nbi * cp + nbr * sp;
        }
        float* st = g_states + (size_t)row * (Q_ * 4) + q * 4;
        st[0] = ar; st[1] = ai; st[2] = br; st[3] = bi;
    }
}

// ---------------------------------------------------------------------------
// mma.sync / cp.async helpers
// ---------------------------------------------------------------------------
__device__ __forceinline__ void ldmat_x4(unsigned int* r, const __nv_bfloat16* p)
{
    unsigned int a = (unsigned int)__cvta_generic_to_shared(p);
    asm volatile("ldmatrix.sync.aligned.m8n8.x4.shared.b16 {%0,%1,%2,%3}, [%4];"
                 : "=r"(r[0]), "=r"(r[1]), "=r"(r[2]), "=r"(r[3]) : "r"(a));
}
__device__ __forceinline__ void ldmat_x4t(unsigned int* r, const __nv_bfloat16* p)
{
    unsigned int a = (unsigned int)__cvta_generic_to_shared(p);
    asm volatile("ldmatrix.sync.aligned.m8n8.x4.trans.shared.b16 {%0,%1,%2,%3}, [%4];"
                 : "=r"(r[0]), "=r"(r[1]), "=r"(r[2]), "=r"(r[3]) : "r"(a));
}
__device__ __forceinline__ void mma16816(float* d, const unsigned int* a, const unsigned int* b)
{
    asm volatile(
        "mma.sync.aligned.m16n8k16.row.col.f32.bf16.bf16.f32 "
        "{%0,%1,%2,%3}, {%4,%5,%6,%7}, {%8,%9}, {%0,%1,%2,%3};"
        : "+f"(d[0]), "+f"(d[1]), "+f"(d[2]), "+f"(d[3])
        : "r"(a[0]), "r"(a[1]), "r"(a[2]), "r"(a[3]), "r"(b[0]), "r"(b[1]));
}
__device__ __forceinline__ void cp16p(__nv_bfloat16* dst, const __nv_bfloat16* src)
{
    unsigned int d = (unsigned int)__cvta_generic_to_shared(dst);
    asm volatile("cp.async.cg.shared.global [%0], [%1], 16;" :: "r"(d), "l"(src));
}
__device__ __forceinline__ void cp_commit()
{
    asm volatile("cp.async.commit_group;");
}
template <int N>
__device__ __forceinline__ void cp_wait()
{
    asm volatile("cp.async.wait_group %0;" :: "n"(N));
}

// ---------------------------------------------------------------------------
// bf16-split GEMM, cp.async double-buffered, term-major MMA ordering.
// C = (Ah+Al)(Bh+Bl) ~= AhBh + AhBl + AlBh
// A row-major [M,K], B row-major [K,N]. 128x128x32 tile, 256 thr (8 warps).
// ---------------------------------------------------------------------------
#define A_SZ (128 * 40)
#define B_SZ (32 * 136)
#define GEMM_SMEM_BYTES ((4 * A_SZ + 4 * B_SZ) * 2)

extern __shared__ __nv_bfloat16 g_dyn[];

__global__ __launch_bounds__(256)
void gemm_bf16s(const __nv_bfloat16* __restrict__ Ah, const __nv_bfloat16* __restrict__ Al,
                const __nv_bfloat16* __restrict__ Bh, const __nv_bfloat16* __restrict__ Bl,
                const float* __restrict__ bias,
                float* __restrict__ Cf,
                __nv_bfloat16* __restrict__ Ch, __nv_bfloat16* __restrict__ Cl,
                int M, int N, int K,
                long long sA, long long sB, long long sC)
{
    __nv_bfloat16* smAh[2];
    __nv_bfloat16* smAl[2];
    __nv_bfloat16* smBh[2];
    __nv_bfloat16* smBl[2];
    smAh[0] = g_dyn;
    smAh[1] = g_dyn + A_SZ;
    smAl[0] = g_dyn + 2 * A_SZ;
    smAl[1] = g_dyn + 3 * A_SZ;
    smBh[0] = g_dyn + 4 * A_SZ;
    smBh[1] = g_dyn + 4 * A_SZ + B_SZ;
    smBl[0] = g_dyn + 4 * A_SZ + 2 * B_SZ;
    smBl[1] = g_dyn + 4 * A_SZ + 3 * B_SZ;

    const int tid  = threadIdx.x;
    const int warp = tid >> 5;
    const int lane = tid & 31;
    const int warp_m = warp & 1;
    const int warp_n = warp >> 1;
    const int m_base = warp_m * 64;
    const int n_base = warp_n * 32;

    const long long z = blockIdx.z;
    const __nv_bfloat16* Ahp = Ah + z * sA + (long long)blockIdx.y * 128 * K;
    const __nv_bfloat16* Alp = Al + z * sA + (long long)blockIdx.y * 128 * K;
    const __nv_bfloat16* Bhp = Bh + z * sB + blockIdx.x * 128;
    const __nv_bfloat16* Blp = Bl + z * sB + blockIdx.x * 128;

    const int ar0 = tid >> 1, ac0 = (tid & 1) * 16;
    const int br0 = tid >> 4, bc0 = (tid & 15) * 8;

    float acc[4][4][4];
    for (int a = 0; a < 4; a++)
        for (int b = 0; b < 4; b++)
            for (int c = 0; c < 4; c++)
                acc[a][b][c] = 0.f;

    const int lm_row = lane & 15;
    const int lm_col = (lane >> 4) * 8;
    const int nIter = K / 32;

    #define LOAD_STAGE(st, k0)                                                  \
    {                                                                           \
        long long ga = (long long)ar0 * K + (k0) + ac0;                         \
        cp16p(smAh[st] + ar0 * 40 + ac0,     Ahp + ga);                         \
        cp16p(smAh[st] + ar0 * 40 + ac0 + 8, Ahp + ga + 8);                     \
        cp16p(smAl[st] + ar0 * 40 + ac0,     Alp + ga);                         \
        cp16p(smAl[st] + ar0 * 40 + ac0 + 8, Alp + ga + 8);                     \
        long long gb0 = (long long)((k0) + br0) * N + bc0;                      \
        long long gb1 = (long long)((k0) + br0 + 16) * N + bc0;                 \
        cp16p(smBh[st] + br0 * 136 + bc0,        Bhp + gb0);                    \
        cp16p(smBh[st] + (br0 + 16) * 136 + bc0, Bhp + gb1);                    \
        cp16p(smBl[st] + br0 * 136 + bc0,        Blp + gb0);                    \
        cp16p(smBl[st] + (br0 + 16) * 136 + bc0, Blp + gb1);                    \
        cp_commit();                                                            \
    }

    LOAD_STAGE(0, 0);

    for (int it = 0; it < nIter; it++) {
        const int cur = it & 1;
        cp_wait<0>();
        __syncthreads();
        if (it + 1 < nIter) {
            LOAD_STAGE(cur ^ 1, (it + 1) * 32);
        }

        #pragma unroll
        for (int kk = 0; kk < 2; kk++) {
            const int ks = kk * 16;
            unsigned int ahf[4][4], alf[4][4], bhf[4][2], blf[4][2];
            #pragma unroll
            for (int mt = 0; mt < 4; mt++) {
                ldmat_x4(ahf[mt], smAh[cur] + (m_base + mt * 16 + lm_row) * 40 + ks + lm_col);
                ldmat_x4(alf[mt], smAl[cur] + (m_base + mt * 16 + lm_row) * 40 + ks + lm_col);
            }
            #pragma unroll
            for (int ng = 0; ng < 2; ng++) {
                unsigned int t[4];
                ldmat_x4t(t, smBh[cur] + (ks + lm_row) * 136 + n_base + ng * 16 + lm_col);
                bhf[2 * ng][0]     = t[0];
                bhf[2 * ng][1]     = t[1];
                bhf[2 * ng + 1][0] = t[2];
                bhf[2 * ng + 1][1] = t[3];
                ldmat_x4t(t, smBl[cur] + (ks + lm_row) * 136 + n_base + ng * 16 + lm_col);
                blf[2 * ng][0]     = t[0];
                blf[2 * ng][1]     = t[1];
                blf[2 * ng + 1][0] = t[2];
                blf[2 * ng + 1][1] = t[3];
            }
            #pragma unroll
            for (int mt = 0; mt < 4; mt++)
                #pragma unroll
                for (int nt = 0; nt < 4; nt++)
                    mma16816(acc[mt][nt], ahf[mt], bhf[nt]);
            #pragma unroll
            for (int mt = 0; mt < 4; mt++)
                #pragma unroll
                for (int nt = 0; nt < 4; nt++)
                    mma16816(acc[mt][nt], ahf[mt], blf[nt]);
            #pragma unroll
            for (int mt = 0; mt < 4; mt++)
                #pragma unroll
                for (int nt = 0; nt < 4; nt++)
                    mma16816(acc[mt][nt], alf[mt], bhf[nt]);
        }
    }

    // epilogue
    const int grp = lane >> 2;
    const int tq  = lane & 3;
    const long long crow0 = (long long)blockIdx.y * 128;
    const int ccol0 = blockIdx.x * 128;
    float* Cfp = Cf ? (Cf + z * sC) : (float*)0;
    __nv_bfloat16* Chp = Ch ? (Ch + z * sC) : (__nv_bfloat16*)0;
    __nv_bfloat16* Clp = Cl ? (Cl + z * sC) : (__nv_bfloat16*)0;

    for (int mt = 0; mt < 4; mt++) {
        for (int nt = 0; nt < 4; nt++) {
            int c = ccol0 + n_base + nt * 8 + 2 * tq;
            float b0 = bias ? bias[c] : 0.f;
            float b1 = bias ? bias[c + 1] : 0.f;
            for (int half = 0; half < 2; half++) {
                long long r = crow0 + m_base + mt * 16 + grp + half * 8;
                float v0 = acc[mt][nt][2 * half + 0] + b0;
                float v1 = acc[mt][nt][2 * half + 1] + b1;
                if (Cfp) {
                    float2 v;
                    v.x = v0; v.y = v1;
                    *(float2*)(Cfp + r * N + c) = v;
                }
                if (Chp) {
                    __nv_bfloat16 h0, h1, l0, l1;
                    split2(v0, h0, l0);
                    split2(v1, h1, l1);
                    __nv_bfloat162 p;
                    p.x = h0; p.y = h1;
                    *(__nv_bfloat162*)(Chp + r * N + c) = p;
                    p.x = l0; p.y = l1;
                    *(__nv_bfloat162*)(Clp + r * N + c) = p;
                }
            }
        }
    }
}

// ---------------------------------------------------------------------------
// attn v2: warp-per-row, 8 rows/block, batch states cached in padded smem,
// register-resident j-tile, warp-shuffle softmax, __expf. blk0 = block offset.
// ---------------------------------------------------------------------------
#define SROW 33                               // padded floats per state row
#define ATTN_SMEM_BYTES ((S_ * SROW + 2 * S_) * 4)   // 71680

__global__ __launch_bounds__(256)
void attn_kernel(float* __restrict__ attn, int blk0)
{
    float* sst = (float*)g_dyn;               // [S_][SROW]
    float* scp = sst + S_ * SROW;             // [S_]
    float* ssp = scp + S_;                    // [S_]

    const int tid  = threadIdx.x;
    const int warp = tid >> 5;
    const int lane = tid & 31;

    const int blk = blockIdx.x + blk0;
    const int b   = blk >> 6;                 // 64 blocks per batch
    const int i0  = (blk & 63) * 8;
    const float* st_b = g_states + (size_t)b * S_ * 32;

    for (int idx = tid; idx < S_ * 8; idx += 256) {
        int row = idx >> 3;
        int c4  = (idx & 7) * 4;
        float4 v = *(const float4*)(st_b + row * 32 + c4);
        float* d = sst + row * SROW + c4;
        d[0] = v.x; d[1] = v.y; d[2] = v.z; d[3] = v.w;
    }
    for (int j = tid; j < S_; j += 256) {
        scp[j] = g_cphi[j];
        ssp[j] = g_sphi[j];
    }
    __syncthreads();

    const int i = i0 + warp;

    float si[32];
    #pragma unroll
    for (int k = 0; k < 32; k++)
        si[k] = sst[i * SROW + k];
    const float ci  = scp[i];
    const float sii = ssp[i];

    float Kv[16];
    float m = -1e30f;
    #pragma unroll
    for (int jj = 0; jj < 16; jj++) {
        const int j = lane + jj * 32;
        const float* sj = sst + j * SROW;
        float p = 1.f;
        #pragma unroll
        for (int q = 0; q < Q_; q++) {
            float air = si[q * 4 + 0], aii = si[q * 4 + 1];
            float bir = si[q * 4 + 2], bii = si[q * 4 + 3];
            float ajr = sj[q * 4 + 0], aji = sj[q * 4 + 1];
            float bjr = sj[q * 4 + 2], bji = sj[q * 4 + 3];
            float re = air * ajr + aii * aji + bir * bjr + bii * bji;
            float im = air * aji - aii * ajr + bir * bji - bii * bjr;
            p *= re * re + im * im;
        }
        float v = p + ci * scp[j] + sii * ssp[j];
        Kv[jj] = v;
        m = fmaxf(m, v);
    }
    #pragma unroll
    for (int off = 16; off; off >>= 1)
        m = fmaxf(m, __shfl_xor_sync(0xffffffffu, m, off));

    float sum = 0.f;
    #pragma unroll
    for (int jj = 0; jj < 16; jj++) {
        float e = __expf(Kv[jj] - m);
        Kv[jj] = e;
        sum += e;
    }
    #pragma unroll
    for (int off = 16; off; off >>= 1)
        sum += __shfl_xor_sync(0xffffffffu, sum, off);
    const float inv = 1.f / sum;

    const size_t row = (size_t)b * S_ + i;
    float* arow = attn + row * S_;
    __nv_bfloat16* hrow = g_Ath + row * S_;
    __nv_bfloat16* lrow = g_Atl + row * S_;
    #pragma unroll
    for (int jj = 0; jj < 16; jj++) {
        const int j = lane + jj * 32;
        float v = Kv[jj] * inv;
        arow[j] = v;
        __nv_bfloat16 h, l;
        split2(v, h, l);
        hrow[j] = h;
        lrow[j] = l;
    }
}

// ---------------------------------------------------------------------------
// launch: weight branch on s1; X-chain split into two batch-halves on the
// main stream and s2 so U-GEMM work starts early. out-GEMM joins everything.
// ---------------------------------------------------------------------------
extern "C" void kernel_launch(void* const* d_in, const int* in_sizes, int n_in,
                              void* d_out, int out_size)
{
    const float* X     = (const float*)d_in[0];
    const float* Wq    = (const float*)d_in[1];
    const float* bq    = (const float*)d_in[2];
    const float* Wv    = (const float*)d_in[3];
    const float* bv    = (const float*)d_in[4];
    const float* Wo    = (const float*)d_in[5];
    const float* bo    = (const float*)d_in[6];
    const float* theta = (const float*)d_in[7];
    const float* phi   = (const float*)d_in[8];

    float* out  = (float*)d_out;
    float* attn = (float*)d_out + OUT_ELEMS;

    (void)in_sizes;
    (void)n_in;
    (void)out_size;

    __nv_bfloat16 *Xh, *Xl, *Wvh, *Wvl, *Woh, *Wol, *W2h, *W2l, *Ath, *Atl, *Uh, *Ul;
    float* b2;
    cudaGetSymbolAddress((void**)&Xh,  g_Xh);
    cudaGetSymbolAddress((void**)&Xl,  g_Xl);
    cudaGetSymbolAddress((void**)&Wvh, g_Wvh);
    cudaGetSymbolAddress((void**)&Wvl, g_Wvl);
    cudaGetSymbolAddress((void**)&Woh, g_Woh);
    cudaGetSymbolAddress((void**)&Wol, g_Wol);
    cudaGetSymbolAddress((void**)&W2h, g_W2h);
    cudaGetSymbolAddress((void**)&W2l, g_W2l);
    cudaGetSymbolAddress((void**)&Ath, g_Ath);
    cudaGetSymbolAddress((void**)&Atl, g_Atl);
    cudaGetSymbolAddress((void**)&Uh,  g_Uh);
    cudaGetSymbolAddress((void**)&Ul,  g_Ul);
    cudaGetSymbolAddress((void**)&b2,  g_b2);

    static cudaStream_t s1 = 0, s2 = 0;
    static cudaEvent_t  evRoot = 0, evW2 = 0, evPhi = 0, evC1 = 0;
    static int s_init_done = 0;
    if (!s_init_done) {
        cudaFuncSetAttribute(gemm_bf16s,
                             cudaFuncAttributeMaxDynamicSharedMemorySize,
                             GEMM_SMEM_BYTES);
        cudaFuncSetAttribute(attn_kernel,
                             cudaFuncAttributeMaxDynamicSharedMemorySize,
                             ATTN_SMEM_BYTES);
        cudaStreamCreateWithFlags(&s1, cudaStreamNonBlocking);
        cudaStreamCreateWithFlags(&s2, cudaStreamNonBlocking);
        cudaEventCreateWithFlags(&evRoot, cudaEventDisableTiming);
        cudaEventCreateWithFlags(&evW2,   cudaEventDisableTiming);
        cudaEventCreateWithFlags(&evPhi,  cudaEventDisableTiming);
        cudaEventCreateWithFlags(&evC1,   cudaEventDisableTiming);
        s_init_done = 1;
    }

    const long long halfA = (long long)HALF_B * S_ * S_;   // attn elems per half
    const long long halfU = (long long)HALF_B * S_ * E_;   // U/X elems per half

    // ---- fork ----
    cudaEventRecord(evRoot, 0);
    cudaStreamWaitEvent(s1, evRoot, 0);
    cudaStreamWaitEvent(s2, evRoot, 0);

    // ---- weight branch on s1 ----
    split_fp32_kernel<<<(E_ * E_ / 4 + 255) / 256, 256, 0, s1>>>(Wv, Wvh, Wvl, E_ * E_);
    split_fp32_kernel<<<(E_ * E_ / 4 + 255) / 256, 256, 0, s1>>>(Wo, Woh, Wol, E_ * E_);
    {
        dim3 gp(E_ / 256, B2_KSPLIT);
        bias2_part_kernel<<<gp, 256, 0, s1>>>(bv, Wo);
        bias2_reduce_kernel<<<E_ / 256, 256, 0, s1>>>(bo);
    }
    {
        dim3 grid(E_ / 128, E_ / 128, 1);
        gemm_bf16s<<<grid, 256, GEMM_SMEM_BYTES, s1>>>(Wvh, Wvl, Woh, Wol, (const float*)0,
                                                       (float*)0, W2h, W2l,
                                                       E_, E_, E_, 0, 0, 0);
    }
    cudaEventRecord(evW2, s1);

    // ---- chunk 0 (batches 0-7) on main stream ----
    phis_kernel<<<1, S_>>>(phi);
    cudaEventRecord(evPhi, 0);

    qsplit_kernel<<<HALF_B * S_ / 8, 256>>>(X, Wq, bq, theta, Xh, Xl, 0);
    attn_kernel<<<HALF_B * S_ / 8, 256, ATTN_SMEM_BYTES>>>(attn, 0);
    {
        dim3 grid(E_ / 128, S_ / 128, HALF_B);
        gemm_bf16s<<<grid, 256, GEMM_SMEM_BYTES>>>(Ath, Atl, Xh, Xl, (const float*)0,
                                                   (float*)0, Uh, Ul,
                                                   S_, E_, S_,
                                                   (long long)S_ * S_,
                                                   (long long)S_ * E_,
                                                   (long long)S_ * E_);
    }

    // ---- chunk 1 (batches 8-15) on s2 ----
    cudaStreamWaitEvent(s2, evPhi, 0);
    qsplit_kernel<<<HALF_B * S_ / 8, 256, 0, s2>>>(X, Wq, bq, theta, Xh, Xl, HALF_B * S_);
    attn_kernel<<<HALF_B * S_ / 8, 256, ATTN_SMEM_BYTES, s2>>>(attn, HALF_B * S_ / 8);
    {
        dim3 grid(E_ / 128, S_ / 128, HALF_B);
        gemm_bf16s<<<grid, 256, GEMM_SMEM_BYTES, s2>>>(Ath + halfA, Atl + halfA,
                                                       Xh + halfU, Xl + halfU,
                                                       (const float*)0,
                                                       (float*)0, Uh + halfU, Ul + halfU,
                                                       S_, E_, S_,
                                                       (long long)S_ * S_,
                                                       (long long)S_ * E_,
                                                       (long long)S_ * E_);
    }
    cudaEventRecord(evC1, s2);

    // ---- join: final GEMM needs U (both halves) + W2 + b2 ----
    cudaStreamWaitEvent(0, evW2, 0);
    cudaStreamWaitEvent(0, evC1, 0);
    {
        dim3 grid(E_ / 128, BS_ROWS / 128, 1);
        gemm_bf16s<<<grid, 256, GEMM_SMEM_BYTES>>>(Uh, Ul, W2h, W2l, b2,
                                                   out, (__nv_bfloat16*)0, (__nv_bfloat16*)0,
                                                   BS_ROWS, E_, E_, 0, 0, 0);
    }
}

// round 14
// speedup vs baseline: 1.4957x; 1.0939x over previous
#include <cuda_runtime.h>
#include <cuda_bf16.h>
#include <stdint.h>
#include <math.h>

// Problem shapes (fixed per reference)
#define B_ 16
#define S_ 512
#define E_ 1024
#define Q_ 8
#define L_ 4

#define BS_ROWS (B_ * S_)            // 8192
#define OUT_ELEMS (B_ * S_ * E_)     // 8388608

#define B2_KSPLIT 32                 // k-chunks for bias2
#define HALF_B (B_ / 2)              // 8 batches per chunk

// ---------------------------------------------------------------------------
// Scratch (device globals: allocation-free rule). 16B-aligned for uint4 I/O.
// ---------------------------------------------------------------------------
__device__ __align__(16) float g_states[BS_ROWS * Q_ * 4];
__device__ __align__(16) float g_cphi[S_];
__device__ __align__(16) float g_sphi[S_];
__device__ __align__(16) float g_b2[E_];                  // bv@Wo + bo
__device__ __align__(16) float g_b2p[B2_KSPLIT * E_];     // partials

__device__ __align__(16) __nv_bfloat16 g_Xh[BS_ROWS * E_];
__device__ __align__(16) __nv_bfloat16 g_Xl[BS_ROWS * E_];
__device__ __align__(16) __nv_bfloat16 g_Wvh[E_ * E_];
__device__ __align__(16) __nv_bfloat16 g_Wvl[E_ * E_];
__device__ __align__(16) __nv_bfloat16 g_Woh[E_ * E_];
__device__ __align__(16) __nv_bfloat16 g_Wol[E_ * E_];
__device__ __align__(16) __nv_bfloat16 g_W2h[E_ * E_];    // (Wv@Wo) split
__device__ __align__(16) __nv_bfloat16 g_W2l[E_ * E_];
__device__ __align__(16) __nv_bfloat16 g_Ath[B_ * S_ * S_];
__device__ __align__(16) __nv_bfloat16 g_Atl[B_ * S_ * S_];
__device__ __align__(16) __nv_bfloat16 g_Uh[BS_ROWS * E_];  // (attn@X) split
__device__ __align__(16) __nv_bfloat16 g_Ul[BS_ROWS * E_];

__device__ __forceinline__ void split2(float v, __nv_bfloat16 &h, __nv_bfloat16 &l)
{
    h = __float2bfloat16(v);
    l = __float2bfloat16(v - __bfloat162float(h));
}

// ---------------------------------------------------------------------------
// Split fp32 -> bf16 hi/lo (vectorized) — for Wv, Wo
// ---------------------------------------------------------------------------
__global__ void split_fp32_kernel(const float* __restrict__ src,
                                  __nv_bfloat16* __restrict__ h,
                                  __nv_bfloat16* __restrict__ l, int n)
{
    int i = (blockIdx.x * blockDim.x + threadIdx.x) * 4;
    if (i >= n) return;
    float4 v = *(const float4*)(src + i);
    __nv_bfloat16 h0, h1, h2, h3, l0, l1, l2, l3;
    split2(v.x, h0, l0);
    split2(v.y, h1, l1);
    split2(v.z, h2, l2);
    split2(v.w, h3, l3);
    __nv_bfloat162 p;
    p.x = h0; p.y = h1; *(__nv_bfloat162*)(h + i)     = p;
    p.x = h2; p.y = h3; *(__nv_bfloat162*)(h + i + 2) = p;
    p.x = l0; p.y = l1; *(__nv_bfloat162*)(l + i)     = p;
    p.x = l2; p.y = l3; *(__nv_bfloat162*)(l + i + 2) = p;
}

// ---------------------------------------------------------------------------
// Precompute cos(phi)/sin(phi); b2 = bv@Wo + bo in two phases
// ---------------------------------------------------------------------------
__global__ void phis_kernel(const float* __restrict__ phi)
{
    int j = threadIdx.x;
    float p = phi[j];
    g_cphi[j] = cosf(p);
    g_sphi[j] = sinf(p);
}

__global__ void bias2_part_kernel(const float* __restrict__ bv,
                                  const float* __restrict__ Wo)
{
    int n  = blockIdx.x * 256 + threadIdx.x;
    int k0 = blockIdx.y * (E_ / B2_KSPLIT);
    float acc = 0.f;
    #pragma unroll 4
    for (int k = k0; k < k0 + E_ / B2_KSPLIT; k++)
        acc += bv[k] * Wo[(size_t)k * E_ + n];
    g_b2p[blockIdx.y * E_ + n] = acc;
}

__global__ void bias2_reduce_kernel(const float* __restrict__ bo)
{
    int n = blockIdx.x * 256 + threadIdx.x;
    float acc = bo[n];
    #pragma unroll
    for (int ky = 0; ky < B2_KSPLIT; ky++)
        acc += g_b2p[ky * E_ + n];
    g_b2[n] = acc;
}

// ---------------------------------------------------------------------------
// Kernel 1: fused X split + quantum_input + qubit recursion (vectorized).
// row0 = starting row of this chunk.
// ---------------------------------------------------------------------------
__global__ __launch_bounds__(256)
void qsplit_kernel(const float* __restrict__ X,
                   const float* __restrict__ Wq,
                   const float* __restrict__ bq,
                   const float* __restrict__ theta,
                   __nv_bfloat16* __restrict__ Xh,
                   __nv_bfloat16* __restrict__ Xl,
                   int row0)
{
    __shared__ float sWq[Q_][E_];

    const int tid  = threadIdx.x;
    const int warp = tid >> 5;
    const int lane = tid & 31;

    for (int idx = tid; idx < E_ * Q_; idx += 256) {
        int e = idx >> 3;
        int q = idx & 7;
        sWq[q][e] = Wq[idx];
    }
    __syncthreads();

    const int row = row0 + blockIdx.x * 8 + warp;
    const float* x = X + (size_t)row * E_;
    __nv_bfloat16* xh = Xh + (size_t)row * E_;
    __nv_bfloat16* xl = Xl + (size_t)row * E_;

    float acc[Q_];
    #pragma unroll
    for (int q = 0; q < Q_; q++) acc[q] = 0.f;

    for (int e0 = lane * 4; e0 < E_; e0 += 128) {
        float4 xv = *(const float4*)(x + e0);
        __nv_bfloat16 h0, h1, h2, h3, l0, l1, l2, l3;
        split2(xv.x, h0, l0);
        split2(xv.y, h1, l1);
        split2(xv.z, h2, l2);
        split2(xv.w, h3, l3);
        __nv_bfloat162 p;
        p.x = h0; p.y = h1; *(__nv_bfloat162*)(xh + e0)     = p;
        p.x = h2; p.y = h3; *(__nv_bfloat162*)(xh + e0 + 2) = p;
        p.x = l0; p.y = l1; *(__nv_bfloat162*)(xl + e0)     = p;
        p.x = l2; p.y = l3; *(__nv_bfloat162*)(xl + e0 + 2) = p;
        #pragma unroll
        for (int q = 0; q < Q_; q++) {
            float4 w = *(const float4*)&sWq[q][e0];
            acc[q] += xv.x * w.x + xv.y * w.y + xv.z * w.z + xv.w * w.w;
        }
    }
    #pragma unroll
    for (int q = 0; q < Q_; q++)
        for (int off = 16; off; off >>= 1)
            acc[q] += __shfl_xor_sync(0xffffffffu, acc[q], off);

    if (lane < Q_) {
        int q = lane;
        float ang = acc[q] + bq[q];
        float ar = cosf(0.5f * ang);
        float ai = 0.f;
        float br = sinf(0.5f * ang);
        float bi = 0.f;
        for (int l = 0; l < L_; l++) {
            float t0 = 0.5f * theta[(l * Q_ + q) * 2 + 0];
            float t1 = 0.5f * theta[(l * Q_ + q) * 2 + 1];
            float c = cosf(t0), s = sinf(t0);
            float nar = c * ar - s * br, nai = c * ai - s * bi;
            float nbr = s * ar + c * br, nbi = s * ai + c * bi;
            float cp = cosf(t1), sp = sinf(t1);
            ar = nar * cp + nai * sp;
            ai = nai * cp - nar * sp;
            br = nbr * cp - nbi * sp;
            bi = nbi * cp + nbr * sp;
        }
        float* st = g_states + (size_t)row * (Q_ * 4) + q * 4;
        st[0] = ar; st[1] = ai; st[2] = br; st[3] = bi;
    }
}

// ---------------------------------------------------------------------------
// mma.sync / cp.async helpers
// ---------------------------------------------------------------------------
__device__ __forceinline__ void ldmat_x4(unsigned int* r, const __nv_bfloat16* p)
{
    unsigned int a = (unsigned int)__cvta_generic_to_shared(p);
    asm volatile("ldmatrix.sync.aligned.m8n8.x4.shared.b16 {%0,%1,%2,%3}, [%4];"
                 : "=r"(r[0]), "=r"(r[1]), "=r"(r[2]), "=r"(r[3]) : "r"(a));
}
__device__ __forceinline__ void ldmat_x4t(unsigned int* r, const __nv_bfloat16* p)
{
    unsigned int a = (unsigned int)__cvta_generic_to_shared(p);
    asm volatile("ldmatrix.sync.aligned.m8n8.x4.trans.shared.b16 {%0,%1,%2,%3}, [%4];"
                 : "=r"(r[0]), "=r"(r[1]), "=r"(r[2]), "=r"(r[3]) : "r"(a));
}
__device__ __forceinline__ void mma16816(float* d, const unsigned int* a, const unsigned int* b)
{
    asm volatile(
        "mma.sync.aligned.m16n8k16.row.col.f32.bf16.bf16.f32 "
        "{%0,%1,%2,%3}, {%4,%5,%6,%7}, {%8,%9}, {%0,%1,%2,%3};"
        : "+f"(d[0]), "+f"(d[1]), "+f"(d[2]), "+f"(d[3])
        : "r"(a[0]), "r"(a[1]), "r"(a[2]), "r"(a[3]), "r"(b[0]), "r"(b[1]));
}
__device__ __forceinline__ void cp16p(__nv_bfloat16* dst, const __nv_bfloat16* src)
{
    unsigned int d = (unsigned int)__cvta_generic_to_shared(dst);
    asm volatile("cp.async.cg.shared.global [%0], [%1], 16;" :: "r"(d), "l"(src));
}
__device__ __forceinline__ void cp_commit()
{
    asm volatile("cp.async.commit_group;");
}
template <int N>
__device__ __forceinline__ void cp_wait()
{
    asm volatile("cp.async.wait_group %0;" :: "n"(N));
}

// ---------------------------------------------------------------------------
// bf16-split GEMM, cp.async double-buffered, term-major MMA ordering.
// C = (Ah+Al)(Bh+Bl) ~= AhBh + AhBl + AlBh
// A row-major [M,K], B row-major [K,N]. 128x128x32 tile, 256 thr (8 warps).
// ---------------------------------------------------------------------------
#define A_SZ (128 * 40)
#define B_SZ (32 * 136)
#define GEMM_SMEM_BYTES ((4 * A_SZ + 4 * B_SZ) * 2)

extern __shared__ __nv_bfloat16 g_dyn[];

__global__ __launch_bounds__(256)
void gemm_bf16s(const __nv_bfloat16* __restrict__ Ah, const __nv_bfloat16* __restrict__ Al,
                const __nv_bfloat16* __restrict__ Bh, const __nv_bfloat16* __restrict__ Bl,
                const float* __restrict__ bias,
                float* __restrict__ Cf,
                __nv_bfloat16* __restrict__ Ch, __nv_bfloat16* __restrict__ Cl,
                int M, int N, int K,
                long long sA, long long sB, long long sC)
{
    __nv_bfloat16* smAh[2];
    __nv_bfloat16* smAl[2];
    __nv_bfloat16* smBh[2];
    __nv_bfloat16* smBl[2];
    smAh[0] = g_dyn;
    smAh[1] = g_dyn + A_SZ;
    smAl[0] = g_dyn + 2 * A_SZ;
    smAl[1] = g_dyn + 3 * A_SZ;
    smBh[0] = g_dyn + 4 * A_SZ;
    smBh[1] = g_dyn + 4 * A_SZ + B_SZ;
    smBl[0] = g_dyn + 4 * A_SZ + 2 * B_SZ;
    smBl[1] = g_dyn + 4 * A_SZ + 3 * B_SZ;

    const int tid  = threadIdx.x;
    const int warp = tid >> 5;
    const int lane = tid & 31;
    const int warp_m = warp & 1;
    const int warp_n = warp >> 1;
    const int m_base = warp_m * 64;
    const int n_base = warp_n * 32;

    const long long z = blockIdx.z;
    const __nv_bfloat16* Ahp = Ah + z * sA + (long long)blockIdx.y * 128 * K;
    const __nv_bfloat16* Alp = Al + z * sA + (long long)blockIdx.y * 128 * K;
    const __nv_bfloat16* Bhp = Bh + z * sB + blockIdx.x * 128;
    const __nv_bfloat16* Blp = Bl + z * sB + blockIdx.x * 128;

    const int ar0 = tid >> 1, ac0 = (tid & 1) * 16;
    const int br0 = tid >> 4, bc0 = (tid & 15) * 8;

    float acc[4][4][4];
    for (int a = 0; a < 4; a++)
        for (int b = 0; b < 4; b++)
            for (int c = 0; c < 4; c++)
                acc[a][b][c] = 0.f;

    const int lm_row = lane & 15;
    const int lm_col = (lane >> 4) * 8;
    const int nIter = K / 32;

    #define LOAD_STAGE(st, k0)                                                  \
    {                                                                           \
        long long ga = (long long)ar0 * K + (k0) + ac0;                         \
        cp16p(smAh[st] + ar0 * 40 + ac0,     Ahp + ga);                         \
        cp16p(smAh[st] + ar0 * 40 + ac0 + 8, Ahp + ga + 8);                     \
        cp16p(smAl[st] + ar0 * 40 + ac0,     Alp + ga);                         \
        cp16p(smAl[st] + ar0 * 40 + ac0 + 8, Alp + ga + 8);                     \
        long long gb0 = (long long)((k0) + br0) * N + bc0;                      \
        long long gb1 = (long long)((k0) + br0 + 16) * N + bc0;                 \
        cp16p(smBh[st] + br0 * 136 + bc0,        Bhp + gb0);                    \
        cp16p(smBh[st] + (br0 + 16) * 136 + bc0, Bhp + gb1);                    \
        cp16p(smBl[st] + br0 * 136 + bc0,        Blp + gb0);                    \
        cp16p(smBl[st] + (br0 + 16) * 136 + bc0, Blp + gb1);                    \
        cp_commit();                                                            \
    }

    LOAD_STAGE(0, 0);

    for (int it = 0; it < nIter; it++) {
        const int cur = it & 1;
        cp_wait<0>();
        __syncthreads();
        if (it + 1 < nIter) {
            LOAD_STAGE(cur ^ 1, (it + 1) * 32);
        }

        #pragma unroll
        for (int kk = 0; kk < 2; kk++) {
            const int ks = kk * 16;
            unsigned int ahf[4][4], alf[4][4], bhf[4][2], blf[4][2];
            #pragma unroll
            for (int mt = 0; mt < 4; mt++) {
                ldmat_x4(ahf[mt], smAh[cur] + (m_base + mt * 16 + lm_row) * 40 + ks + lm_col);
                ldmat_x4(alf[mt], smAl[cur] + (m_base + mt * 16 + lm_row) * 40 + ks + lm_col);
            }
            #pragma unroll
            for (int ng = 0; ng < 2; ng++) {
                unsigned int t[4];
                ldmat_x4t(t, smBh[cur] + (ks + lm_row) * 136 + n_base + ng * 16 + lm_col);
                bhf[2 * ng][0]     = t[0];
                bhf[2 * ng][1]     = t[1];
                bhf[2 * ng + 1][0] = t[2];
                bhf[2 * ng + 1][1] = t[3];
                ldmat_x4t(t, smBl[cur] + (ks + lm_row) * 136 + n_base + ng * 16 + lm_col);
                blf[2 * ng][0]     = t[0];
                blf[2 * ng][1]     = t[1];
                blf[2 * ng + 1][0] = t[2];
                blf[2 * ng + 1][1] = t[3];
            }
            #pragma unroll
            for (int mt = 0; mt < 4; mt++)
                #pragma unroll
                for (int nt = 0; nt < 4; nt++)
                    mma16816(acc[mt][nt], ahf[mt], bhf[nt]);
            #pragma unroll
            for (int mt = 0; mt < 4; mt++)
                #pragma unroll
                for (int nt = 0; nt < 4; nt++)
                    mma16816(acc[mt][nt], ahf[mt], blf[nt]);
            #pragma unroll
            for (int mt = 0; mt < 4; mt++)
                #pragma unroll
                for (int nt = 0; nt < 4; nt++)
                    mma16816(acc[mt][nt], alf[mt], bhf[nt]);
        }
    }

    // epilogue
    const int grp = lane >> 2;
    const int tq  = lane & 3;
    const long long crow0 = (long long)blockIdx.y * 128;
    const int ccol0 = blockIdx.x * 128;
    float* Cfp = Cf ? (Cf + z * sC) : (float*)0;
    __nv_bfloat16* Chp = Ch ? (Ch + z * sC) : (__nv_bfloat16*)0;
    __nv_bfloat16* Clp = Cl ? (Cl + z * sC) : (__nv_bfloat16*)0;

    for (int mt = 0; mt < 4; mt++) {
        for (int nt = 0; nt < 4; nt++) {
            int c = ccol0 + n_base + nt * 8 + 2 * tq;
            float b0 = bias ? bias[c] : 0.f;
            float b1 = bias ? bias[c + 1] : 0.f;
            for (int half = 0; half < 2; half++) {
                long long r = crow0 + m_base + mt * 16 + grp + half * 8;
                float v0 = acc[mt][nt][2 * half + 0] + b0;
                float v1 = acc[mt][nt][2 * half + 1] + b1;
                if (Cfp) {
                    float2 v;
                    v.x = v0; v.y = v1;
                    *(float2*)(Cfp + r * N + c) = v;
                }
                if (Chp) {
                    __nv_bfloat16 h0, h1, l0, l1;
                    split2(v0, h0, l0);
                    split2(v1, h1, l1);
                    __nv_bfloat162 p;
                    p.x = h0; p.y = h1;
                    *(__nv_bfloat162*)(Chp + r * N + c) = p;
                    p.x = l0; p.y = l1;
                    *(__nv_bfloat162*)(Clp + r * N + c) = p;
                }
            }
        }
    }
}

// ---------------------------------------------------------------------------
// attn v2: warp-per-row, 8 rows/block, batch states cached in padded smem,
// register-resident j-tile, warp-shuffle softmax, __expf. blk0 = block offset.
// ---------------------------------------------------------------------------
#define SROW 33                               // padded floats per state row
#define ATTN_SMEM_BYTES ((S_ * SROW + 2 * S_) * 4)   // 71680

__global__ __launch_bounds__(256)
void attn_kernel(float* __restrict__ attn, int blk0)
{
    float* sst = (float*)g_dyn;               // [S_][SROW]
    float* scp = sst + S_ * SROW;             // [S_]
    float* ssp = scp + S_;                    // [S_]

    const int tid  = threadIdx.x;
    const int warp = tid >> 5;
    const int lane = tid & 31;

    const int blk = blockIdx.x + blk0;
    const int b   = blk >> 6;                 // 64 blocks per batch
    const int i0  = (blk & 63) * 8;
    const float* st_b = g_states + (size_t)b * S_ * 32;

    for (int idx = tid; idx < S_ * 8; idx += 256) {
        int row = idx >> 3;
        int c4  = (idx & 7) * 4;
        float4 v = *(const float4*)(st_b + row * 32 + c4);
        float* d = sst + row * SROW + c4;
        d[0] = v.x; d[1] = v.y; d[2] = v.z; d[3] = v.w;
    }
    for (int j = tid; j < S_; j += 256) {
        scp[j] = g_cphi[j];
        ssp[j] = g_sphi[j];
    }
    __syncthreads();

    const int i = i0 + warp;

    float si[32];
    #pragma unroll
    for (int k = 0; k < 32; k++)
        si[k] = sst[i * SROW + k];
    const float ci  = scp[i];
    const float sii = ssp[i];

    float Kv[16];
    float m = -1e30f;
    #pragma unroll
    for (int jj = 0; jj < 16; jj++) {
        const int j = lane + jj * 32;
        const float* sj = sst + j * SROW;
        float p = 1.f;
        #pragma unroll
        for (int q = 0; q < Q_; q++) {
            float air = si[q * 4 + 0], aii = si[q * 4 + 1];
            float bir = si[q * 4 + 2], bii = si[q * 4 + 3];
            float ajr = sj[q * 4 + 0], aji = sj[q * 4 + 1];
            float bjr = sj[q * 4 + 2], bji = sj[q * 4 + 3];
            float re = air * ajr + aii * aji + bir * bjr + bii * bji;
            float im = air * aji - aii * ajr + bir * bji - bii * bjr;
            p *= re * re + im * im;
        }
        float v = p + ci * scp[j] + sii * ssp[j];
        Kv[jj] = v;
        m = fmaxf(m, v);
    }
    #pragma unroll
    for (int off = 16; off; off >>= 1)
        m = fmaxf(m, __shfl_xor_sync(0xffffffffu, m, off));

    float sum = 0.f;
    #pragma unroll
    for (int jj = 0; jj < 16; jj++) {
        float e = __expf(Kv[jj] - m);
        Kv[jj] = e;
        sum += e;
    }
    #pragma unroll
    for (int off = 16; off; off >>= 1)
        sum += __shfl_xor_sync(0xffffffffu, sum, off);
    const float inv = 1.f / sum;

    const size_t row = (size_t)b * S_ + i;
    float* arow = attn + row * S_;
    __nv_bfloat16* hrow = g_Ath + row * S_;
    __nv_bfloat16* lrow = g_Atl + row * S_;
    #pragma unroll
    for (int jj = 0; jj < 16; jj++) {
        const int j = lane + jj * 32;
        float v = Kv[jj] * inv;
        arow[j] = v;
        __nv_bfloat16 h, l;
        split2(v, h, l);
        hrow[j] = h;
        lrow[j] = l;
    }
}

// ---------------------------------------------------------------------------
// launch: weight branch on s1; X-chain AND out-GEMM split into two batch
// halves across main stream + s2, so tensor work is packed end to end.
// ---------------------------------------------------------------------------
extern "C" void kernel_launch(void* const* d_in, const int* in_sizes, int n_in,
                              void* d_out, int out_size)
{
    const float* X     = (const float*)d_in[0];
    const float* Wq    = (const float*)d_in[1];
    const float* bq    = (const float*)d_in[2];
    const float* Wv    = (const float*)d_in[3];
    const float* bv    = (const float*)d_in[4];
    const float* Wo    = (const float*)d_in[5];
    const float* bo    = (const float*)d_in[6];
    const float* theta = (const float*)d_in[7];
    const float* phi   = (const float*)d_in[8];

    float* out  = (float*)d_out;
    float* attn = (float*)d_out + OUT_ELEMS;

    (void)in_sizes;
    (void)n_in;
    (void)out_size;

    __nv_bfloat16 *Xh, *Xl, *Wvh, *Wvl, *Woh, *Wol, *W2h, *W2l, *Ath, *Atl, *Uh, *Ul;
    float* b2;
    cudaGetSymbolAddress((void**)&Xh,  g_Xh);
    cudaGetSymbolAddress((void**)&Xl,  g_Xl);
    cudaGetSymbolAddress((void**)&Wvh, g_Wvh);
    cudaGetSymbolAddress((void**)&Wvl, g_Wvl);
    cudaGetSymbolAddress((void**)&Woh, g_Woh);
    cudaGetSymbolAddress((void**)&Wol, g_Wol);
    cudaGetSymbolAddress((void**)&W2h, g_W2h);
    cudaGetSymbolAddress((void**)&W2l, g_W2l);
    cudaGetSymbolAddress((void**)&Ath, g_Ath);
    cudaGetSymbolAddress((void**)&Atl, g_Atl);
    cudaGetSymbolAddress((void**)&Uh,  g_Uh);
    cudaGetSymbolAddress((void**)&Ul,  g_Ul);
    cudaGetSymbolAddress((void**)&b2,  g_b2);

    static cudaStream_t s1 = 0, s2 = 0;
    static cudaEvent_t  evRoot = 0, evW2 = 0, evPhi = 0, evOut1 = 0;
    static int s_init_done = 0;
    if (!s_init_done) {
        cudaFuncSetAttribute(gemm_bf16s,
                             cudaFuncAttributeMaxDynamicSharedMemorySize,
                             GEMM_SMEM_BYTES);
        cudaFuncSetAttribute(attn_kernel,
                             cudaFuncAttributeMaxDynamicSharedMemorySize,
                             ATTN_SMEM_BYTES);
        cudaStreamCreateWithFlags(&s1, cudaStreamNonBlocking);
        cudaStreamCreateWithFlags(&s2, cudaStreamNonBlocking);
        cudaEventCreateWithFlags(&evRoot, cudaEventDisableTiming);
        cudaEventCreateWithFlags(&evW2,   cudaEventDisableTiming);
        cudaEventCreateWithFlags(&evPhi,  cudaEventDisableTiming);
        cudaEventCreateWithFlags(&evOut1, cudaEventDisableTiming);
        s_init_done = 1;
    }

    const long long halfA = (long long)HALF_B * S_ * S_;   // attn elems per half
    const long long halfU = (long long)HALF_B * S_ * E_;   // U/X/out elems per half

    // ---- fork ----
    cudaEventRecord(evRoot, 0);
    cudaStreamWaitEvent(s1, evRoot, 0);
    cudaStreamWaitEvent(s2, evRoot, 0);

    // ---- weight branch on s1 ----
    split_fp32_kernel<<<(E_ * E_ / 4 + 255) / 256, 256, 0, s1>>>(Wv, Wvh, Wvl, E_ * E_);
    split_fp32_kernel<<<(E_ * E_ / 4 + 255) / 256, 256, 0, s1>>>(Wo, Woh, Wol, E_ * E_);
    {
        dim3 gp(E_ / 256, B2_KSPLIT);
        bias2_part_kernel<<<gp, 256, 0, s1>>>(bv, Wo);
        bias2_reduce_kernel<<<E_ / 256, 256, 0, s1>>>(bo);
    }
    {
        dim3 grid(E_ / 128, E_ / 128, 1);
        gemm_bf16s<<<grid, 256, GEMM_SMEM_BYTES, s1>>>(Wvh, Wvl, Woh, Wol, (const float*)0,
                                                       (float*)0, W2h, W2l,
                                                       E_, E_, E_, 0, 0, 0);
    }
    cudaEventRecord(evW2, s1);

    // ---- chunk 0 (batches 0-7) on main stream ----
    phis_kernel<<<1, S_>>>(phi);
    cudaEventRecord(evPhi, 0);

    qsplit_kernel<<<HALF_B * S_ / 8, 256>>>(X, Wq, bq, theta, Xh, Xl, 0);
    attn_kernel<<<HALF_B * S_ / 8, 256, ATTN_SMEM_BYTES>>>(attn, 0);
    {
        dim3 grid(E_ / 128, S_ / 128, HALF_B);
        gemm_bf16s<<<grid, 256, GEMM_SMEM_BYTES>>>(Ath, Atl, Xh, Xl, (const float*)0,
                                                   (float*)0, Uh, Ul,
                                                   S_, E_, S_,
                                                   (long long)S_ * S_,
                                                   (long long)S_ * E_,
                                                   (long long)S_ * E_);
    }

    // ---- chunk 1 (batches 8-15) on s2 ----
    cudaStreamWaitEvent(s2, evPhi, 0);
    qsplit_kernel<<<HALF_B * S_ / 8, 256, 0, s2>>>(X, Wq, bq, theta, Xh, Xl, HALF_B * S_);
    attn_kernel<<<HALF_B * S_ / 8, 256, ATTN_SMEM_BYTES, s2>>>(attn, HALF_B * S_ / 8);
    {
        dim3 grid(E_ / 128, S_ / 128, HALF_B);
        gemm_bf16s<<<grid, 256, GEMM_SMEM_BYTES, s2>>>(Ath + halfA, Atl + halfA,
                                                       Xh + halfU, Xl + halfU,
                                                       (const float*)0,
                                                       (float*)0, Uh + halfU, Ul + halfU,
                                                       S_, E_, S_,
                                                       (long long)S_ * S_,
                                                       (long long)S_ * E_,
                                                       (long long)S_ * E_);
    }

    // ---- out chunk 0 on main stream: needs U0 + W2 ----
    cudaStreamWaitEvent(0, evW2, 0);
    {
        dim3 grid(E_ / 128, (HALF_B * S_) / 128, 1);
        gemm_bf16s<<<grid, 256, GEMM_SMEM_BYTES>>>(Uh, Ul, W2h, W2l, b2,
                                                   out, (__nv_bfloat16*)0, (__nv_bfloat16*)0,
                                                   HALF_B * S_, E_, E_, 0, 0, 0);
    }

    // ---- out chunk 1 on s2: needs U1 + W2 ----
    cudaStreamWaitEvent(s2, evW2, 0);
    {
        dim3 grid(E_ / 128, (HALF_B * S_) / 128, 1);
        gemm_bf16s<<<grid, 256, GEMM_SMEM_BYTES, s2>>>(Uh + halfU, Ul + halfU, W2h, W2l, b2,
                                                       out + halfU,
                                                       (__nv_bfloat16*)0, (__nv_bfloat16*)0,
                                                       HALF_B * S_, E_, E_, 0, 0, 0);
    }
    cudaEventRecord(evOut1, s2);

    // ---- join ----
    cudaStreamWaitEvent(0, evOut1, 0);
}